// round 1
// baseline (speedup 1.0000x reference)
#include <cuda_runtime.h>
#include <math.h>

// ---------------------------------------------------------------------------
// TxtNet: 4x conv1d (K=1,2,3,7, replication pad) + tanh -> concat(x1,x2,x3,x3,x7)
//         -> linear 1500->512 + tanh.
// Key folding: x5==x3, so effective linear weight is [1200,512] with
// slp_w[:,600:900]+slp_w[:,900:1200] merged. Conv stage = 13 shifted GEMM taps.
// B=32, L=512, C=300, H=512. Positions P = 16384.
// ---------------------------------------------------------------------------

#define TM 128
#define TN 64
#define KC 12
#define P_TOT 16384

// Scratch (static device globals — no runtime allocation)
__device__ float g_h[P_TOT * 1200];        // conv outputs, tanh'd: [pos][1200]
__device__ float g_wpack[13 * 300 * 300];  // per-tap weights: [tap][ic][oc]
__device__ float g_weff[1200 * 512];       // folded linear weight: [ic][oc]
__device__ float g_bpack[1200];            // conv biases packed per channel

__constant__ int c_tap_off[13] = {0,  0, 1,  -1, 0, 1,  -3, -2, -1, 0, 1, 2, 3};
__constant__ int c_conv_base[4] = {0, 1, 3, 6};
__constant__ int c_conv_ntap[4] = {1, 2, 3, 7};

// ---------------------------------------------------------------------------
// Prep 1: transpose conv weights into per-tap [ic][oc] (oc contiguous)
// ---------------------------------------------------------------------------
__global__ void pack_weights_kernel(const float* __restrict__ w1,
                                    const float* __restrict__ w2,
                                    const float* __restrict__ w3,
                                    const float* __restrict__ w7) {
    int idx = blockIdx.x * blockDim.x + threadIdx.x;
    if (idx >= 13 * 90000) return;
    int t = idx / 90000;
    int r = idx % 90000;
    int ic = r / 300, oc = r % 300;
    const float* w;
    int K, k;
    if (t < 1)      { w = w1; K = 1; k = t; }
    else if (t < 3) { w = w2; K = 2; k = t - 1; }
    else if (t < 6) { w = w3; K = 3; k = t - 3; }
    else            { w = w7; K = 7; k = t - 6; }
    g_wpack[idx] = w[(oc * 300 + ic) * K + k];
}

// ---------------------------------------------------------------------------
// Prep 2: folded linear weight (x5==x3 fold) + packed conv biases
// ---------------------------------------------------------------------------
__global__ void pack_weff_kernel(const float* __restrict__ slp_w,
                                 const float* __restrict__ b1,
                                 const float* __restrict__ b2,
                                 const float* __restrict__ b3,
                                 const float* __restrict__ b7) {
    int idx = blockIdx.x * blockDim.x + threadIdx.x;
    if (idx < 1200 * 512) {
        int ic = idx / 512, oc = idx % 512;
        float v;
        if (ic < 600)       v = slp_w[oc * 1500 + ic];
        else if (ic < 900)  v = slp_w[oc * 1500 + ic] + slp_w[oc * 1500 + ic + 300];
        else                v = slp_w[oc * 1500 + ic + 300];  // x7 block (cols 1200:1500)
        g_weff[idx] = v;
    }
    if (idx < 1200) {
        int conv = idx / 300, oc = idx % 300;
        const float* b = (conv == 0) ? b1 : (conv == 1) ? b2 : (conv == 2) ? b3 : b7;
        g_bpack[idx] = b[oc];
    }
}

// ---------------------------------------------------------------------------
// Stage 1: conv GEMM. Grid: x = conv(4) * nTile(5), y = M tile (128 of them).
// Each block: TM=128 positions x TN=64 out channels; loops over taps, each tap
// is a [TM,300]x[300,TN] GEMM with shifted+clamped input rows.
// ---------------------------------------------------------------------------
__global__ __launch_bounds__(256)
void conv_gemm_kernel(const float* __restrict__ x) {
    __shared__ __align__(16) float As[TM][KC + 1];
    __shared__ __align__(16) float Bs[KC][TN];

    const int conv = blockIdx.x / 5;
    const int oc0  = (blockIdx.x % 5) * TN;
    const int pos0 = blockIdx.y * TM;
    const int bidx = pos0 >> 9;       // batch (128 | 512, tile never crosses batch)
    const int l0   = pos0 & 511;
    const float* xb = x + (size_t)bidx * 512 * 300;

    const int tx = threadIdx.x, ty = threadIdx.y;
    const int tid = ty * 16 + tx;

    float acc[8][4];
#pragma unroll
    for (int m = 0; m < 8; ++m)
#pragma unroll
        for (int n = 0; n < 4; ++n) acc[m][n] = 0.f;

    const int ntap = c_conv_ntap[conv];
    const int tbase = c_conv_base[conv];

    for (int tt = 0; tt < ntap; ++tt) {
        const int t = tbase + tt;
        const int off = c_tap_off[t];
        const float* wp = g_wpack + t * 90000;

        for (int c0 = 0; c0 < 300; c0 += KC) {
            __syncthreads();
            // Load A tile: As[i][c] = x[b, clamp(l0+i+off), c0+c]
#pragma unroll
            for (int e = 0; e < (TM * KC) / 256; ++e) {
                int li = e * 256 + tid;
                int i = li / KC, c = li % KC;
                int row = l0 + i + off;
                row = row < 0 ? 0 : (row > 511 ? 511 : row);
                As[i][c] = xb[row * 300 + c0 + c];
            }
            // Load B tile: Bs[c][j] = wpack[t][c0+c][oc0+j] (zero-pad oc>=300)
#pragma unroll
            for (int e = 0; e < (KC * TN) / 256; ++e) {
                int li = e * 256 + tid;
                int c = li / TN, j = li % TN;
                int oc = oc0 + j;
                Bs[c][j] = (oc < 300) ? wp[(c0 + c) * 300 + oc] : 0.f;
            }
            __syncthreads();
#pragma unroll
            for (int cc = 0; cc < KC; ++cc) {
                float a[8];
#pragma unroll
                for (int m = 0; m < 8; ++m) a[m] = As[ty * 8 + m][cc];
                float4 bv = *(const float4*)&Bs[cc][tx * 4];
                float bb[4] = {bv.x, bv.y, bv.z, bv.w};
#pragma unroll
                for (int m = 0; m < 8; ++m)
#pragma unroll
                    for (int n = 0; n < 4; ++n)
                        acc[m][n] = fmaf(a[m], bb[n], acc[m][n]);
            }
        }
    }

    // Epilogue: tanh(acc + bias) -> g_h[pos][conv*300 + oc]
#pragma unroll
    for (int n = 0; n < 4; ++n) {
        int oc = oc0 + tx * 4 + n;
        if (oc >= 300) continue;
        int gc = conv * 300 + oc;
        float bias = g_bpack[gc];
#pragma unroll
        for (int m = 0; m < 8; ++m) {
            int pos = pos0 + ty * 8 + m;
            g_h[(size_t)pos * 1200 + gc] = tanhf(acc[m][n] + bias);
        }
    }
}

// ---------------------------------------------------------------------------
// Stage 2: linear GEMM 16384x1200 @ 1200x512 + bias + tanh.
// Grid: x = N tile (8), y = M tile (128).
// ---------------------------------------------------------------------------
__global__ __launch_bounds__(256)
void slp_gemm_kernel(const float* __restrict__ slp_b, float* __restrict__ out) {
    __shared__ __align__(16) float As[TM][KC + 1];
    __shared__ __align__(16) float Bs[KC][TN];

    const int oc0  = blockIdx.x * TN;
    const int pos0 = blockIdx.y * TM;
    const int tx = threadIdx.x, ty = threadIdx.y;
    const int tid = ty * 16 + tx;

    float acc[8][4];
#pragma unroll
    for (int m = 0; m < 8; ++m)
#pragma unroll
        for (int n = 0; n < 4; ++n) acc[m][n] = 0.f;

    for (int c0 = 0; c0 < 1200; c0 += KC) {
        __syncthreads();
#pragma unroll
        for (int e = 0; e < (TM * KC) / 256; ++e) {
            int li = e * 256 + tid;
            int i = li / KC, c = li % KC;
            As[i][c] = g_h[(size_t)(pos0 + i) * 1200 + c0 + c];
        }
#pragma unroll
        for (int e = 0; e < (KC * TN) / 256; ++e) {
            int li = e * 256 + tid;
            int c = li / TN, j = li % TN;
            Bs[c][j] = g_weff[(c0 + c) * 512 + oc0 + j];
        }
        __syncthreads();
#pragma unroll
        for (int cc = 0; cc < KC; ++cc) {
            float a[8];
#pragma unroll
            for (int m = 0; m < 8; ++m) a[m] = As[ty * 8 + m][cc];
            float4 bv = *(const float4*)&Bs[cc][tx * 4];
            float bb[4] = {bv.x, bv.y, bv.z, bv.w};
#pragma unroll
            for (int m = 0; m < 8; ++m)
#pragma unroll
                for (int n = 0; n < 4; ++n)
                    acc[m][n] = fmaf(a[m], bb[n], acc[m][n]);
        }
    }

#pragma unroll
    for (int n = 0; n < 4; ++n) {
        int oc = oc0 + tx * 4 + n;
        float bias = slp_b[oc];
#pragma unroll
        for (int m = 0; m < 8; ++m) {
            int pos = pos0 + ty * 8 + m;
            out[(size_t)pos * 512 + oc] = tanhf(acc[m][n] + bias);
        }
    }
}

// ---------------------------------------------------------------------------
// kernel_launch: inputs per metadata order:
// 0:x 1:w1 2:b1 3:w2 4:b2 5:w3 6:b3 7:w7 8:b7 9:slp_w 10:slp_b
// ---------------------------------------------------------------------------
extern "C" void kernel_launch(void* const* d_in, const int* in_sizes, int n_in,
                              void* d_out, int out_size) {
    const float* x     = (const float*)d_in[0];
    const float* w1    = (const float*)d_in[1];
    const float* b1    = (const float*)d_in[2];
    const float* w2    = (const float*)d_in[3];
    const float* b2    = (const float*)d_in[4];
    const float* w3    = (const float*)d_in[5];
    const float* b3    = (const float*)d_in[6];
    const float* w7    = (const float*)d_in[7];
    const float* b7    = (const float*)d_in[8];
    const float* slp_w = (const float*)d_in[9];
    const float* slp_b = (const float*)d_in[10];
    float* out = (float*)d_out;

    // Prep: pack weights (transpose to [tap][ic][oc]) and folded linear weight
    {
        int n = 13 * 90000;
        pack_weights_kernel<<<(n + 255) / 256, 256>>>(w1, w2, w3, w7);
    }
    {
        int n = 1200 * 512;
        pack_weff_kernel<<<(n + 255) / 256, 256>>>(slp_w, b1, b2, b3, b7);
    }

    // Stage 1: conv GEMMs -> g_h
    {
        dim3 grid(4 * 5, P_TOT / TM);  // (conv,nTile) x Mtiles
        dim3 block(16, 16);
        conv_gemm_kernel<<<grid, block>>>(x);
    }
    // Stage 2: linear + tanh -> out
    {
        dim3 grid(512 / TN, P_TOT / TM);
        dim3 block(16, 16);
        slp_gemm_kernel<<<grid, block>>>(slp_b, out);
    }
}

// round 3
// speedup vs baseline: 2.2933x; 2.2933x over previous
#include <cuda_runtime.h>
#include <cuda_bf16.h>
#include <math.h>
#include <stdint.h>

// ===========================================================================
// TxtNet via mma.sync (HMMA.16816 bf16) — works on plain sm_103 PTX target.
// Split-bf16: D += Ah*Bh + Ah*Bl + Al*Bh (lo*lo dropped) -> ~fp32 accuracy.
// Stage 1: 4 conv GEMMs, K = ntap*320 (channels padded 300->320, per-tap
//          shifted+clamped A rows). Stage 2: GEMM 16384 x 1216 x 512 with
//          the x5==x3 fold. BM=BN=128, BK=64, 8 warps, double-buffer cp.async.
// ===========================================================================

#define P_TOT 16384
#define SRS   72            // smem row stride in bf16 elements (144 B)
#define BUF_SZ 73728        // 4 tiles * 128*72*2
#define A_H 0
#define A_L 18432
#define B_H 36864
#define B_L 55296
#define SMEM_TOTAL (2 * BUF_SZ)   // 147456

// ------------------------- device scratch (zero-init) ----------------------
__device__ __nv_bfloat16 g_xh[32 * 512 * 320];
__device__ __nv_bfloat16 g_xl[32 * 512 * 320];
__device__ __nv_bfloat16 g_wch[384 * 4160];   // [oc][Koff(conv)+t*320+ic]
__device__ __nv_bfloat16 g_wcl[384 * 4160];
__device__ __nv_bfloat16 g_weh[512 * 1216];   // [oc][ic] folded
__device__ __nv_bfloat16 g_wel[512 * 1216];
__device__ __nv_bfloat16 g_hh[P_TOT * 1216];  // conv out (tanh), hi
__device__ __nv_bfloat16 g_hl[P_TOT * 1216];  // lo (pad cols 1200..1215 stay 0)
__device__ float g_bconv[1200];

__constant__ int c_off[13]  = {0,  0, 1,  -1, 0, 1,  -3, -2, -1, 0, 1, 2, 3};
__constant__ int c_base[4]  = {0, 1, 3, 6};
__constant__ int c_Kc[4]    = {320, 640, 960, 2240};
__constant__ int c_Koff[4]  = {0, 320, 960, 1920};

// ------------------------- helpers -----------------------------------------
__device__ __forceinline__ uint32_t smem_u32(const void* p) {
    uint32_t a;
    asm("{ .reg .u64 t; cvta.to.shared.u64 t, %1; cvt.u32.u64 %0, t; }"
        : "=r"(a) : "l"(p));
    return a;
}
#define CPA(dst, src) \
    asm volatile("cp.async.cg.shared.global [%0], [%1], 16;" \
                 :: "r"(dst), "l"(src) : "memory")
#define CP_COMMIT() asm volatile("cp.async.commit_group;" ::: "memory")
#define CP_WAIT0()  asm volatile("cp.async.wait_group 0;" ::: "memory")
#define CP_WAIT1()  asm volatile("cp.async.wait_group 1;" ::: "memory")

__device__ __forceinline__ void mma16816(float* d, const uint32_t* a,
                                         const uint32_t* b) {
    asm volatile(
        "mma.sync.aligned.m16n8k16.row.col.f32.bf16.bf16.f32 "
        "{%0,%1,%2,%3}, {%4,%5,%6,%7}, {%8,%9}, {%0,%1,%2,%3};"
        : "+f"(d[0]), "+f"(d[1]), "+f"(d[2]), "+f"(d[3])
        : "r"(a[0]), "r"(a[1]), "r"(a[2]), "r"(a[3]), "r"(b[0]), "r"(b[1]));
}

// ------------------------- prep kernels ------------------------------------
__global__ void prep_x(const float* __restrict__ x) {
    int idx = blockIdx.x * 256 + threadIdx.x;
    if (idx >= 32 * 512 * 320) return;
    int c = idx % 320, bl = idx / 320;
    float v = (c < 300) ? x[bl * 300 + c] : 0.f;
    __nv_bfloat16 h = __float2bfloat16(v);
    g_xh[idx] = h;
    g_xl[idx] = __float2bfloat16(v - __bfloat162float(h));
}

__global__ void prep_wc(const float* __restrict__ w1, const float* __restrict__ w2,
                        const float* __restrict__ w3, const float* __restrict__ w7) {
    int idx = blockIdx.x * 256 + threadIdx.x;
    if (idx >= 384 * 4160) return;
    int oc = idx / 4160, kall = idx % 4160;
    float v = 0.f;
    int conv, r;
    if (kall < 320)       { conv = 0; r = kall; }
    else if (kall < 960)  { conv = 1; r = kall - 320; }
    else if (kall < 1920) { conv = 2; r = kall - 960; }
    else                  { conv = 3; r = kall - 1920; }
    int t = r / 320, ic = r % 320;
    if (oc < 300 && ic < 300) {
        if (conv == 0)      v = w1[(oc * 300 + ic)];
        else if (conv == 1) v = w2[(oc * 300 + ic) * 2 + t];
        else if (conv == 2) v = w3[(oc * 300 + ic) * 3 + t];
        else                v = w7[(oc * 300 + ic) * 7 + t];
    }
    __nv_bfloat16 h = __float2bfloat16(v);
    g_wch[idx] = h;
    g_wcl[idx] = __float2bfloat16(v - __bfloat162float(h));
}

__global__ void prep_we(const float* __restrict__ slp_w,
                        const float* __restrict__ b1, const float* __restrict__ b2,
                        const float* __restrict__ b3, const float* __restrict__ b7) {
    int idx = blockIdx.x * 256 + threadIdx.x;
    if (idx < 512 * 1216) {
        int oc = idx / 1216, ic = idx % 1216;
        float v = 0.f;
        if (ic < 600)       v = slp_w[oc * 1500 + ic];
        else if (ic < 900)  v = slp_w[oc * 1500 + ic] + slp_w[oc * 1500 + ic + 300];
        else if (ic < 1200) v = slp_w[oc * 1500 + ic + 300];
        __nv_bfloat16 h = __float2bfloat16(v);
        g_weh[idx] = h;
        g_wel[idx] = __float2bfloat16(v - __bfloat162float(h));
    }
    if (idx < 1200) {
        int conv = idx / 300, oc = idx % 300;
        const float* b = (conv == 0) ? b1 : (conv == 1) ? b2 : (conv == 2) ? b3 : b7;
        g_bconv[idx] = b[oc];
    }
}

// ------------------------- core compute macro ------------------------------
// Per k16 step: load A frags (hi/lo) once, then stream B frags over 8 n-tiles.
#define COMPUTE_BUF(base)                                                      \
    do {                                                                       \
        const char* Ahp = (base) + A_H;                                        \
        const char* Alp = (base) + A_L;                                        \
        const char* Bhp = (base) + B_H;                                        \
        const char* Blp = (base) + B_L;                                        \
        _Pragma("unroll")                                                      \
        for (int kk = 0; kk < 4; ++kk) {                                       \
            uint32_t ah[2][4], al[2][4];                                       \
            const int cA = (kk * 16 + kp2) * 2;                                \
            _Pragma("unroll")                                                  \
            for (int mt = 0; mt < 2; ++mt) {                                   \
                int r0 = (wm * 32 + mt * 16 + quad) * 144;                     \
                ah[mt][0] = *(const uint32_t*)(Ahp + r0 + cA);                 \
                ah[mt][1] = *(const uint32_t*)(Ahp + r0 + 8 * 144 + cA);       \
                ah[mt][2] = *(const uint32_t*)(Ahp + r0 + cA + 16);            \
                ah[mt][3] = *(const uint32_t*)(Ahp + r0 + 8 * 144 + cA + 16);  \
                al[mt][0] = *(const uint32_t*)(Alp + r0 + cA);                 \
                al[mt][1] = *(const uint32_t*)(Alp + r0 + 8 * 144 + cA);       \
                al[mt][2] = *(const uint32_t*)(Alp + r0 + cA + 16);            \
                al[mt][3] = *(const uint32_t*)(Alp + r0 + 8 * 144 + cA + 16);  \
            }                                                                  \
            _Pragma("unroll")                                                  \
            for (int nt = 0; nt < 8; ++nt) {                                   \
                int nb = (wn * 64 + nt * 8 + quad) * 144;                      \
                uint32_t bh[2], bl[2];                                         \
                bh[0] = *(const uint32_t*)(Bhp + nb + cA);                     \
                bh[1] = *(const uint32_t*)(Bhp + nb + cA + 16);                \
                bl[0] = *(const uint32_t*)(Blp + nb + cA);                     \
                bl[1] = *(const uint32_t*)(Blp + nb + cA + 16);                \
                _Pragma("unroll")                                              \
                for (int mt = 0; mt < 2; ++mt) {                               \
                    mma16816(acc[mt][nt], ah[mt], bh);                         \
                    mma16816(acc[mt][nt], ah[mt], bl);                         \
                    mma16816(acc[mt][nt], al[mt], bh);                         \
                }                                                              \
            }                                                                  \
        }                                                                      \
    } while (0)

// ------------------------- conv GEMM kernel --------------------------------
__global__ __launch_bounds__(256, 1)
void conv_mma_kernel() {
    extern __shared__ char sm[];
    const int tid = threadIdx.x, lane = tid & 31, wid = tid >> 5;
    const int wm = wid & 3, wn = wid >> 2;
    const int quad = lane >> 2, kp2 = (lane & 3) * 2;

    const int conv = blockIdx.x / 3;
    const int oc0  = (blockIdx.x % 3) * 128;
    const int pos0 = blockIdx.y * 128;
    const int bat = pos0 >> 9, l0 = pos0 & 511;
    const int nc = c_Kc[conv] >> 6;
    const int koff = c_Koff[conv];
    const int tb = c_base[conv];
    const __nv_bfloat16* Axh = g_xh + (size_t)bat * 512 * 320;
    const __nv_bfloat16* Axl = g_xl + (size_t)bat * 512 * 320;

    float acc[2][8][4];
#pragma unroll
    for (int mt = 0; mt < 2; ++mt)
#pragma unroll
        for (int nt = 0; nt < 8; ++nt)
#pragma unroll
            for (int e = 0; e < 4; ++e) acc[mt][nt][e] = 0.f;

    auto load_chunk = [&](int ch, int bufi) {
        const int k0 = ch * 64;
        const int tl = k0 / 320, c0 = k0 - tl * 320;
        const int off = c_off[tb + tl];
        const uint32_t sbase = smem_u32(sm) + bufi * BUF_SZ;
#pragma unroll
        for (int s = 0; s < 4; ++s) {
            int idx = s * 256 + tid;
            int row = idx >> 3, seg = idx & 7;
            uint32_t so = row * 144 + seg * 16;
            int rr = l0 + row + off;
            rr = rr < 0 ? 0 : (rr > 511 ? 511 : rr);
            size_t ga = (size_t)rr * 320 + c0 + seg * 8;
            CPA(sbase + A_H + so, Axh + ga);
            CPA(sbase + A_L + so, Axl + ga);
            size_t gb = (size_t)(oc0 + row) * 4160 + koff + k0 + seg * 8;
            CPA(sbase + B_H + so, g_wch + gb);
            CPA(sbase + B_L + so, g_wcl + gb);
        }
    };

    load_chunk(0, 0);
    CP_COMMIT();
    for (int ch = 0; ch < nc; ++ch) {
        int buf = ch & 1;
        if (ch + 1 < nc) { load_chunk(ch + 1, buf ^ 1); CP_COMMIT(); CP_WAIT1(); }
        else CP_WAIT0();
        __syncthreads();
        const char* base = sm + buf * BUF_SZ;
        COMPUTE_BUF(base);
        __syncthreads();
    }

    // epilogue: tanh(acc + bias) -> hi/lo bf16
#pragma unroll
    for (int mt = 0; mt < 2; ++mt) {
        int r0 = pos0 + wm * 32 + mt * 16 + quad;
#pragma unroll
        for (int nt = 0; nt < 8; ++nt) {
            int col = oc0 + wn * 64 + nt * 8 + kp2;
            if (col >= 300) continue;
            int gc = conv * 300 + col;
            float bi0 = g_bconv[gc], bi1 = g_bconv[gc + 1];
#pragma unroll
            for (int half = 0; half < 2; ++half) {
                int r = r0 + half * 8;
                float v0 = tanhf(acc[mt][nt][half * 2 + 0] + bi0);
                float v1 = tanhf(acc[mt][nt][half * 2 + 1] + bi1);
                __nv_bfloat16 h0 = __float2bfloat16(v0);
                __nv_bfloat16 h1 = __float2bfloat16(v1);
                __nv_bfloat162 hv; hv.x = h0; hv.y = h1;
                __nv_bfloat162 lv;
                lv.x = __float2bfloat16(v0 - __bfloat162float(h0));
                lv.y = __float2bfloat16(v1 - __bfloat162float(h1));
                *(__nv_bfloat162*)(g_hh + (size_t)r * 1216 + gc) = hv;
                *(__nv_bfloat162*)(g_hl + (size_t)r * 1216 + gc) = lv;
            }
        }
    }
}

// ------------------------- SLP GEMM kernel ---------------------------------
__global__ __launch_bounds__(256, 1)
void slp_mma_kernel(const float* __restrict__ slp_b, float* __restrict__ out) {
    extern __shared__ char sm[];
    const int tid = threadIdx.x, lane = tid & 31, wid = tid >> 5;
    const int wm = wid & 3, wn = wid >> 2;
    const int quad = lane >> 2, kp2 = (lane & 3) * 2;
    const int oc0  = blockIdx.x * 128;
    const int pos0 = blockIdx.y * 128;
    const int nc = 1216 / 64;  // 19

    float acc[2][8][4];
#pragma unroll
    for (int mt = 0; mt < 2; ++mt)
#pragma unroll
        for (int nt = 0; nt < 8; ++nt)
#pragma unroll
            for (int e = 0; e < 4; ++e) acc[mt][nt][e] = 0.f;

    auto load_chunk = [&](int ch, int bufi) {
        const int k0 = ch * 64;
        const uint32_t sbase = smem_u32(sm) + bufi * BUF_SZ;
#pragma unroll
        for (int s = 0; s < 4; ++s) {
            int idx = s * 256 + tid;
            int row = idx >> 3, seg = idx & 7;
            uint32_t so = row * 144 + seg * 16;
            size_t ga = (size_t)(pos0 + row) * 1216 + k0 + seg * 8;
            CPA(sbase + A_H + so, g_hh + ga);
            CPA(sbase + A_L + so, g_hl + ga);
            size_t gb = (size_t)(oc0 + row) * 1216 + k0 + seg * 8;
            CPA(sbase + B_H + so, g_weh + gb);
            CPA(sbase + B_L + so, g_wel + gb);
        }
    };

    load_chunk(0, 0);
    CP_COMMIT();
    for (int ch = 0; ch < nc; ++ch) {
        int buf = ch & 1;
        if (ch + 1 < nc) { load_chunk(ch + 1, buf ^ 1); CP_COMMIT(); CP_WAIT1(); }
        else CP_WAIT0();
        __syncthreads();
        const char* base = sm + buf * BUF_SZ;
        COMPUTE_BUF(base);
        __syncthreads();
    }

#pragma unroll
    for (int mt = 0; mt < 2; ++mt) {
        int r0 = pos0 + wm * 32 + mt * 16 + quad;
#pragma unroll
        for (int nt = 0; nt < 8; ++nt) {
            int col = oc0 + wn * 64 + nt * 8 + kp2;
            float bi0 = slp_b[col], bi1 = slp_b[col + 1];
#pragma unroll
            for (int half = 0; half < 2; ++half) {
                int r = r0 + half * 8;
                float2 v;
                v.x = tanhf(acc[mt][nt][half * 2 + 0] + bi0);
                v.y = tanhf(acc[mt][nt][half * 2 + 1] + bi1);
                *(float2*)(out + (size_t)r * 512 + col) = v;
            }
        }
    }
}

// ------------------------- launch ------------------------------------------
extern "C" void kernel_launch(void* const* d_in, const int* in_sizes, int n_in,
                              void* d_out, int out_size) {
    const float* x     = (const float*)d_in[0];
    const float* w1    = (const float*)d_in[1];
    const float* b1    = (const float*)d_in[2];
    const float* w2    = (const float*)d_in[3];
    const float* b2    = (const float*)d_in[4];
    const float* w3    = (const float*)d_in[5];
    const float* b3    = (const float*)d_in[6];
    const float* w7    = (const float*)d_in[7];
    const float* b7    = (const float*)d_in[8];
    const float* slp_w = (const float*)d_in[9];
    const float* slp_b = (const float*)d_in[10];
    float* out = (float*)d_out;

    cudaFuncSetAttribute(conv_mma_kernel, cudaFuncAttributeMaxDynamicSharedMemorySize, SMEM_TOTAL);
    cudaFuncSetAttribute(slp_mma_kernel,  cudaFuncAttributeMaxDynamicSharedMemorySize, SMEM_TOTAL);

    prep_x<<<(32 * 512 * 320 + 255) / 256, 256>>>(x);
    prep_wc<<<(384 * 4160 + 255) / 256, 256>>>(w1, w2, w3, w7);
    prep_we<<<(512 * 1216 + 255) / 256, 256>>>(slp_w, b1, b2, b3, b7);

    conv_mma_kernel<<<dim3(12, 128), 256, SMEM_TOTAL>>>();
    slp_mma_kernel<<<dim3(4, 128), 256, SMEM_TOTAL>>>(slp_b, out);
}

// round 4
// speedup vs baseline: 2.5706x; 1.1209x over previous
#include <cuda_runtime.h>
#include <cuda_bf16.h>
#include <math.h>
#include <stdint.h>

// ===========================================================================
// TxtNet via mma.sync (HMMA.16816 bf16), split-bf16 3-term (lo*lo dropped).
// R4: 512 threads (16 warps, 4x4), ldmatrix fragment loads, conv N-tiles
//     2x160 (was 3x128). Stage1: conv GEMMs K=ntap*320; Stage2: 16384x1216x512.
// ===========================================================================

#define P_TOT 16384

// conv kernel smem: A 128 rows, B 160 rows, 144B row stride, hi+lo, x2 buffers
#define C_AL_D 18432                   // A_L - A_H
#define C_B_O  36864                   // B_H offset
#define C_BL_D 23040                   // B_L - B_H (160*144)
#define C_BUF  82944                   // per-buffer bytes
#define C_SMEM (2 * C_BUF)             // 165888
// slp kernel smem: A 128, B 128
#define S_BL_D 18432
#define S_BUF  73728
#define S_SMEM (2 * S_BUF)             // 147456

// ------------------------- device scratch (zero-init) ----------------------
__device__ __nv_bfloat16 g_xh[32 * 512 * 320];
__device__ __nv_bfloat16 g_xl[32 * 512 * 320];
__device__ __nv_bfloat16 g_wch[384 * 4160];   // [oc][Koff(conv)+t*320+ic]
__device__ __nv_bfloat16 g_wcl[384 * 4160];
__device__ __nv_bfloat16 g_weh[512 * 1216];   // [oc][ic] folded
__device__ __nv_bfloat16 g_wel[512 * 1216];
__device__ __nv_bfloat16 g_hh[P_TOT * 1216];
__device__ __nv_bfloat16 g_hl[P_TOT * 1216];
__device__ float g_bconv[1200];

__constant__ int c_off[13]  = {0,  0, 1,  -1, 0, 1,  -3, -2, -1, 0, 1, 2, 3};
__constant__ int c_base[4]  = {0, 1, 3, 6};
__constant__ int c_Kc[4]    = {320, 640, 960, 2240};
__constant__ int c_Koff[4]  = {0, 320, 960, 1920};

// ------------------------- asm helpers -------------------------------------
__device__ __forceinline__ uint32_t smem_u32(const void* p) {
    uint32_t a;
    asm("{ .reg .u64 t; cvta.to.shared.u64 t, %1; cvt.u32.u64 %0, t; }"
        : "=r"(a) : "l"(p));
    return a;
}
#define CPA(dst, src) \
    asm volatile("cp.async.cg.shared.global [%0], [%1], 16;" \
                 :: "r"(dst), "l"(src) : "memory")
#define CP_COMMIT() asm volatile("cp.async.commit_group;" ::: "memory")
#define CP_WAIT0()  asm volatile("cp.async.wait_group 0;" ::: "memory")
#define CP_WAIT1()  asm volatile("cp.async.wait_group 1;" ::: "memory")
#define LDSM4(R, A) \
    asm volatile("ldmatrix.sync.aligned.m8n8.x4.shared.b16 {%0,%1,%2,%3}, [%4];" \
                 : "=r"((R)[0]), "=r"((R)[1]), "=r"((R)[2]), "=r"((R)[3]) : "r"(A))
#define LDSM2(R, A) \
    asm volatile("ldmatrix.sync.aligned.m8n8.x2.shared.b16 {%0,%1}, [%2];" \
                 : "=r"((R)[0]), "=r"((R)[1]) : "r"(A))

__device__ __forceinline__ void mma16816(float* d, const uint32_t* a,
                                         const uint32_t* b) {
    asm volatile(
        "mma.sync.aligned.m16n8k16.row.col.f32.bf16.bf16.f32 "
        "{%0,%1,%2,%3}, {%4,%5,%6,%7}, {%8,%9}, {%0,%1,%2,%3};"
        : "+f"(d[0]), "+f"(d[1]), "+f"(d[2]), "+f"(d[3])
        : "r"(a[0]), "r"(a[1]), "r"(a[2]), "r"(a[3]), "r"(b[0]), "r"(b[1]));
}

// ------------------------- core compute ------------------------------------
// NT n-subtiles of 8 per warp; BLD = B_L - B_H. Layout: A_H@0, A_L@+18432,
// B_H@36864, B_L@36864+BLD. Row stride 144B, BK=64 (4 k16 steps).
template <int NT, int BLD>
__device__ __forceinline__ void compute_buf(uint32_t sb, float (&acc)[2][NT][4],
                                            int wm, int wn, int lane) {
    const uint32_t aoff  = (lane & 15) * 144 + (lane >> 4) * 16;
    const uint32_t boff4 = ((lane & 7) + ((lane >> 4) & 1) * 8) * 144 +
                           ((lane >> 3) & 1) * 16;
    const uint32_t boff2 = (lane & 7) * 144 + (((lane >> 3) & 1) * 16);
#pragma unroll
    for (int kk = 0; kk < 4; ++kk) {
        const uint32_t kb = kk * 32;
        uint32_t ah[2][4], al[2][4];
#pragma unroll
        for (int mt = 0; mt < 2; ++mt) {
            uint32_t a = sb + (wm * 32 + mt * 16) * 144 + aoff + kb;
            LDSM4(ah[mt], a);
            LDSM4(al[mt], a + C_AL_D);
        }
#pragma unroll
        for (int p = 0; p < NT / 2; ++p) {
            uint32_t b = sb + C_B_O + (wn * (NT * 8) + p * 16) * 144 + boff4 + kb;
            uint32_t bh[4], bl[4];
            LDSM4(bh, b);
            LDSM4(bl, b + BLD);
#pragma unroll
            for (int q = 0; q < 2; ++q) {
#pragma unroll
                for (int mt = 0; mt < 2; ++mt) {
                    mma16816(acc[mt][p * 2 + q], ah[mt], bh + q * 2);
                    mma16816(acc[mt][p * 2 + q], ah[mt], bl + q * 2);
                    mma16816(acc[mt][p * 2 + q], al[mt], bh + q * 2);
                }
            }
        }
        if (NT & 1) {
            uint32_t b = sb + C_B_O + (wn * (NT * 8) + (NT - 1) * 8) * 144 +
                         boff2 + kb;
            uint32_t bh[2], bl[2];
            LDSM2(bh, b);
            LDSM2(bl, b + BLD);
#pragma unroll
            for (int mt = 0; mt < 2; ++mt) {
                mma16816(acc[mt][NT - 1], ah[mt], bh);
                mma16816(acc[mt][NT - 1], ah[mt], bl);
                mma16816(acc[mt][NT - 1], al[mt], bh);
            }
        }
    }
}

// ------------------------- prep kernels ------------------------------------
__global__ void prep_x(const float* __restrict__ x) {
    int idx = blockIdx.x * 256 + threadIdx.x;
    if (idx >= 32 * 512 * 320) return;
    int c = idx % 320, bl = idx / 320;
    float v = (c < 300) ? x[bl * 300 + c] : 0.f;
    __nv_bfloat16 h = __float2bfloat16(v);
    g_xh[idx] = h;
    g_xl[idx] = __float2bfloat16(v - __bfloat162float(h));
}

__global__ void prep_wc(const float* __restrict__ w1, const float* __restrict__ w2,
                        const float* __restrict__ w3, const float* __restrict__ w7) {
    int idx = blockIdx.x * 256 + threadIdx.x;
    if (idx >= 384 * 4160) return;
    int oc = idx / 4160, kall = idx % 4160;
    float v = 0.f;
    int conv, r;
    if (kall < 320)       { conv = 0; r = kall; }
    else if (kall < 960)  { conv = 1; r = kall - 320; }
    else if (kall < 1920) { conv = 2; r = kall - 960; }
    else                  { conv = 3; r = kall - 1920; }
    int t = r / 320, ic = r % 320;
    if (oc < 300 && ic < 300) {
        if (conv == 0)      v = w1[(oc * 300 + ic)];
        else if (conv == 1) v = w2[(oc * 300 + ic) * 2 + t];
        else if (conv == 2) v = w3[(oc * 300 + ic) * 3 + t];
        else                v = w7[(oc * 300 + ic) * 7 + t];
    }
    __nv_bfloat16 h = __float2bfloat16(v);
    g_wch[idx] = h;
    g_wcl[idx] = __float2bfloat16(v - __bfloat162float(h));
}

__global__ void prep_we(const float* __restrict__ slp_w,
                        const float* __restrict__ b1, const float* __restrict__ b2,
                        const float* __restrict__ b3, const float* __restrict__ b7) {
    int idx = blockIdx.x * 256 + threadIdx.x;
    if (idx < 512 * 1216) {
        int oc = idx / 1216, ic = idx % 1216;
        float v = 0.f;
        if (ic < 600)       v = slp_w[oc * 1500 + ic];
        else if (ic < 900)  v = slp_w[oc * 1500 + ic] + slp_w[oc * 1500 + ic + 300];
        else if (ic < 1200) v = slp_w[oc * 1500 + ic + 300];
        __nv_bfloat16 h = __float2bfloat16(v);
        g_weh[idx] = h;
        g_wel[idx] = __float2bfloat16(v - __bfloat162float(h));
    }
    if (idx < 1200) {
        int conv = idx / 300, oc = idx % 300;
        const float* b = (conv == 0) ? b1 : (conv == 1) ? b2 : (conv == 2) ? b3 : b7;
        g_bconv[idx] = b[oc];
    }
}

// ------------------------- conv GEMM kernel (BM=128, BN=160) ---------------
__global__ __launch_bounds__(512, 1)
void conv_mma_kernel() {
    extern __shared__ char sm[];
    const int tid = threadIdx.x, lane = tid & 31, wid = tid >> 5;
    const int wm = wid & 3, wn = wid >> 2;          // 4 x 4 warps
    const int quad = lane >> 2, kp2 = (lane & 3) * 2;

    const int conv = blockIdx.x >> 1;
    const int oc0  = (blockIdx.x & 1) * 160;
    const int pos0 = blockIdx.y * 128;
    const int bat = pos0 >> 9, l0 = pos0 & 511;
    const int nc = c_Kc[conv] >> 6;
    const int koff = c_Koff[conv];
    const int tb = c_base[conv];
    const __nv_bfloat16* Axh = g_xh + (size_t)bat * 512 * 320;
    const __nv_bfloat16* Axl = g_xl + (size_t)bat * 512 * 320;
    const uint32_t smbase = smem_u32(sm);

    float acc[2][5][4];
#pragma unroll
    for (int mt = 0; mt < 2; ++mt)
#pragma unroll
        for (int nt = 0; nt < 5; ++nt)
#pragma unroll
            for (int e = 0; e < 4; ++e) acc[mt][nt][e] = 0.f;

    auto load_chunk = [&](int ch, int bufi) {
        const int k0 = ch * 64;
        const int tl = k0 / 320, c0 = k0 - tl * 320;
        const int off = c_off[tb + tl];
        const uint32_t sbase = smbase + bufi * C_BUF;
        // A: 128 rows x 8 segs (hi+lo)
#pragma unroll
        for (int s = 0; s < 2; ++s) {
            int idx = s * 512 + tid;
            int row = idx >> 3, seg = idx & 7;
            int rr = l0 + row + off;
            rr = rr < 0 ? 0 : (rr > 511 ? 511 : rr);
            size_t ga = (size_t)rr * 320 + c0 + seg * 8;
            uint32_t so = row * 144 + seg * 16;
            CPA(sbase + so, Axh + ga);
            CPA(sbase + C_AL_D + so, Axl + ga);
        }
        // B: 160 rows x 8 segs (hi+lo)
#pragma unroll
        for (int s = 0; s < 3; ++s) {
            int idx = s * 512 + tid;
            if (idx < 1280) {
                int row = idx >> 3, seg = idx & 7;
                size_t gb = (size_t)(oc0 + row) * 4160 + koff + k0 + seg * 8;
                uint32_t so = row * 144 + seg * 16;
                CPA(sbase + C_B_O + so, g_wch + gb);
                CPA(sbase + C_B_O + C_BL_D + so, g_wcl + gb);
            }
        }
    };

    load_chunk(0, 0);
    CP_COMMIT();
    for (int ch = 0; ch < nc; ++ch) {
        int buf = ch & 1;
        if (ch + 1 < nc) { load_chunk(ch + 1, buf ^ 1); CP_COMMIT(); CP_WAIT1(); }
        else CP_WAIT0();
        __syncthreads();
        compute_buf<5, C_BL_D>(smbase + buf * C_BUF, acc, wm, wn, lane);
        __syncthreads();
    }

    // epilogue: tanh(acc + bias) -> hi/lo bf16
#pragma unroll
    for (int mt = 0; mt < 2; ++mt) {
        int r0 = pos0 + wm * 32 + mt * 16 + quad;
#pragma unroll
        for (int nt = 0; nt < 5; ++nt) {
            int col = oc0 + wn * 40 + nt * 8 + kp2;
            if (col >= 300) continue;
            int gc = conv * 300 + col;
            float bi0 = g_bconv[gc], bi1 = g_bconv[gc + 1];
#pragma unroll
            for (int half = 0; half < 2; ++half) {
                int r = r0 + half * 8;
                float v0 = tanhf(acc[mt][nt][half * 2 + 0] + bi0);
                float v1 = tanhf(acc[mt][nt][half * 2 + 1] + bi1);
                __nv_bfloat16 h0 = __float2bfloat16(v0);
                __nv_bfloat16 h1 = __float2bfloat16(v1);
                __nv_bfloat162 hv; hv.x = h0; hv.y = h1;
                __nv_bfloat162 lv;
                lv.x = __float2bfloat16(v0 - __bfloat162float(h0));
                lv.y = __float2bfloat16(v1 - __bfloat162float(h1));
                *(__nv_bfloat162*)(g_hh + (size_t)r * 1216 + gc) = hv;
                *(__nv_bfloat162*)(g_hl + (size_t)r * 1216 + gc) = lv;
            }
        }
    }
}

// ------------------------- SLP GEMM kernel (BM=128, BN=128) ----------------
__global__ __launch_bounds__(512, 1)
void slp_mma_kernel(const float* __restrict__ slp_b, float* __restrict__ out) {
    extern __shared__ char sm[];
    const int tid = threadIdx.x, lane = tid & 31, wid = tid >> 5;
    const int wm = wid & 3, wn = wid >> 2;
    const int quad = lane >> 2, kp2 = (lane & 3) * 2;
    const int oc0  = blockIdx.x * 128;
    const int pos0 = blockIdx.y * 128;
    const int nc = 1216 / 64;  // 19
    const uint32_t smbase = smem_u32(sm);

    float acc[2][4][4];
#pragma unroll
    for (int mt = 0; mt < 2; ++mt)
#pragma unroll
        for (int nt = 0; nt < 4; ++nt)
#pragma unroll
            for (int e = 0; e < 4; ++e) acc[mt][nt][e] = 0.f;

    auto load_chunk = [&](int ch, int bufi) {
        const int k0 = ch * 64;
        const uint32_t sbase = smbase + bufi * S_BUF;
#pragma unroll
        for (int s = 0; s < 2; ++s) {
            int idx = s * 512 + tid;
            int row = idx >> 3, seg = idx & 7;
            uint32_t so = row * 144 + seg * 16;
            size_t ga = (size_t)(pos0 + row) * 1216 + k0 + seg * 8;
            CPA(sbase + so, g_hh + ga);
            CPA(sbase + C_AL_D + so, g_hl + ga);
            size_t gb = (size_t)(oc0 + row) * 1216 + k0 + seg * 8;
            CPA(sbase + C_B_O + so, g_weh + gb);
            CPA(sbase + C_B_O + S_BL_D + so, g_wel + gb);
        }
    };

    load_chunk(0, 0);
    CP_COMMIT();
    for (int ch = 0; ch < nc; ++ch) {
        int buf = ch & 1;
        if (ch + 1 < nc) { load_chunk(ch + 1, buf ^ 1); CP_COMMIT(); CP_WAIT1(); }
        else CP_WAIT0();
        __syncthreads();
        compute_buf<4, S_BL_D>(smbase + buf * S_BUF, acc, wm, wn, lane);
        __syncthreads();
    }

#pragma unroll
    for (int mt = 0; mt < 2; ++mt) {
        int r0 = pos0 + wm * 32 + mt * 16 + quad;
#pragma unroll
        for (int nt = 0; nt < 4; ++nt) {
            int col = oc0 + wn * 32 + nt * 8 + kp2;
            float bi0 = slp_b[col], bi1 = slp_b[col + 1];
#pragma unroll
            for (int half = 0; half < 2; ++half) {
                int r = r0 + half * 8;
                float2 v;
                v.x = tanhf(acc[mt][nt][half * 2 + 0] + bi0);
                v.y = tanhf(acc[mt][nt][half * 2 + 1] + bi1);
                *(float2*)(out + (size_t)r * 512 + col) = v;
            }
        }
    }
}

// ------------------------- launch ------------------------------------------
extern "C" void kernel_launch(void* const* d_in, const int* in_sizes, int n_in,
                              void* d_out, int out_size) {
    const float* x     = (const float*)d_in[0];
    const float* w1    = (const float*)d_in[1];
    const float* b1    = (const float*)d_in[2];
    const float* w2    = (const float*)d_in[3];
    const float* b2    = (const float*)d_in[4];
    const float* w3    = (const float*)d_in[5];
    const float* b3    = (const float*)d_in[6];
    const float* w7    = (const float*)d_in[7];
    const float* b7    = (const float*)d_in[8];
    const float* slp_w = (const float*)d_in[9];
    const float* slp_b = (const float*)d_in[10];
    float* out = (float*)d_out;

    cudaFuncSetAttribute(conv_mma_kernel, cudaFuncAttributeMaxDynamicSharedMemorySize, C_SMEM);
    cudaFuncSetAttribute(slp_mma_kernel,  cudaFuncAttributeMaxDynamicSharedMemorySize, S_SMEM);

    prep_x<<<(32 * 512 * 320 + 255) / 256, 256>>>(x);
    prep_wc<<<(384 * 4160 + 255) / 256, 256>>>(w1, w2, w3, w7);
    prep_we<<<(512 * 1216 + 255) / 256, 256>>>(slp_w, b1, b2, b3, b7);

    conv_mma_kernel<<<dim3(8, 128), 512, C_SMEM>>>();
    slp_mma_kernel<<<dim3(4, 128), 512, S_SMEM>>>(slp_b, out);
}

// round 5
// speedup vs baseline: 3.2576x; 1.2673x over previous
#include <cuda_runtime.h>
#include <cuda_bf16.h>
#include <math.h>
#include <stdint.h>

// ===========================================================================
// TxtNet, split-bf16 (3-term) HMMA.16816 GEMMs fed by cp.async.bulk (UBLKCP).
// All operands re-laid out chunk-major + pre-swizzled (SW128) in GMEM by prep
// kernels, so each 128x64 SMEM tile is ONE contiguous bulk copy.
// Conv: 4 GEMMs, K=ntap*320, tap shift baked into guarded x slabs.
// SLP:  16384 x 1216 x 512 with the x5==x3 fold.
// ===========================================================================

#define P_TOT 16384

// conv smem buffer: A 16K hi + 16K lo, B 20K hi + 20K lo
#define CH_A_H 0
#define CH_A_L 16384
#define CH_B_H 32768
#define CH_B_L 53248
#define CH_BUF 73728
#define CONV_SMEM (2 * CH_BUF + 64)
// slp smem buffer: A 16K hi/lo, B 16K hi/lo
#define SL_A_H 0
#define SL_A_L 16384
#define SL_B_H 32768
#define SL_B_L 49152
#define SL_BUF 65536
#define SLP_SMEM (2 * SL_BUF + 64)

// ------------------------- device scratch (zero-init) ----------------------
// x chunked: [b 32][kc 5][row 528 (8 guard each side)][64], swizzled by row&7
__device__ __nv_bfloat16 g_xch[32 * 5 * 528 * 64];
__device__ __nv_bfloat16 g_xcl[32 * 5 * 528 * 64];
// conv weights chunked: [s 65][oc 320][64], swizzled by oc&7
__device__ __nv_bfloat16 g_wcch[65 * 320 * 64];
__device__ __nv_bfloat16 g_wccl[65 * 320 * 64];
// h chunked: [kc 19][pos 16384][64], swizzled by pos&7 (cols 1200+ stay zero)
__device__ __nv_bfloat16 g_hch[19 * 16384 * 64];
__device__ __nv_bfloat16 g_hcl[19 * 16384 * 64];
// slp weights chunked: [kc 19][oc 512][64], swizzled by oc&7
__device__ __nv_bfloat16 g_wech[19 * 512 * 64];
__device__ __nv_bfloat16 g_wecl[19 * 512 * 64];
__device__ float g_bconv[1200];

__constant__ int c_off[13] = {0,  0, 1,  -1, 0, 1,  -3, -2, -1, 0, 1, 2, 3};
__constant__ int c_base[4] = {0, 1, 3, 6};
__constant__ int c_nch[4]  = {5, 10, 15, 35};   // chunks per conv (tap*5)
__constant__ int c_sb[4]   = {0, 5, 15, 30};    // chunk-slab base per conv

// ------------------------- asm helpers -------------------------------------
__device__ __forceinline__ uint32_t smem_u32(const void* p) {
    uint32_t a;
    asm("{ .reg .u64 t; cvta.to.shared.u64 t, %1; cvt.u32.u64 %0, t; }"
        : "=r"(a) : "l"(p));
    return a;
}
#define BULK_G2S(dst, src, bytes, mbar)                                        \
    asm volatile(                                                              \
        "cp.async.bulk.shared::cluster.global.mbarrier::complete_tx::bytes "   \
        "[%0], [%1], %2, [%3];"                                                \
        :: "r"(dst), "l"(src), "r"(bytes), "r"(mbar) : "memory")
#define MBAR_INIT(a, c) \
    asm volatile("mbarrier.init.shared.b64 [%0], %1;" :: "r"(a), "r"(c) : "memory")
#define MBAR_EXPECT_TX(a, b) \
    asm volatile("mbarrier.arrive.expect_tx.shared.b64 _, [%0], %1;" \
                 :: "r"(a), "r"(b) : "memory")
__device__ __forceinline__ void mbar_wait(uint32_t a, uint32_t ph) {
    asm volatile(
        "{\n .reg .pred P;\nW%=:\n"
        " mbarrier.try_wait.parity.acquire.cta.shared::cta.b64 P, [%0], %1, 0x989680;\n"
        " @!P bra W%=;\n}"
        :: "r"(a), "r"(ph) : "memory");
}
#define LDSM4(R, A) \
    asm volatile("ldmatrix.sync.aligned.m8n8.x4.shared.b16 {%0,%1,%2,%3}, [%4];" \
                 : "=r"((R)[0]), "=r"((R)[1]), "=r"((R)[2]), "=r"((R)[3]) : "r"(A))
#define LDSM2(R, A) \
    asm volatile("ldmatrix.sync.aligned.m8n8.x2.shared.b16 {%0,%1}, [%2];" \
                 : "=r"((R)[0]), "=r"((R)[1]) : "r"(A))

__device__ __forceinline__ void mma16816(float* d, const uint32_t* a,
                                         const uint32_t* b) {
    asm volatile(
        "mma.sync.aligned.m16n8k16.row.col.f32.bf16.bf16.f32 "
        "{%0,%1,%2,%3}, {%4,%5,%6,%7}, {%8,%9}, {%0,%1,%2,%3};"
        : "+f"(d[0]), "+f"(d[1]), "+f"(d[2]), "+f"(d[3])
        : "r"(a[0]), "r"(a[1]), "r"(a[2]), "r"(a[3]), "r"(b[0]), "r"(b[1]));
}

// ------------------------- core compute ------------------------------------
// SMEM tiles: raw 128B row stride, SW128 pre-baked in GMEM. rmA = per-lane A
// swizzle phase ((lane&15)+adj)&7; B phase is lane&7 (tile starts 8-aligned).
template <int NT>
__device__ __forceinline__ void compute_buf(uint32_t Ah, uint32_t Al,
                                            uint32_t Bh, uint32_t Bl,
                                            float (&acc)[2][NT][4],
                                            int wm, int wn, int lane, int rmA) {
    const int hi16 = lane >> 4;
    const int sbB = (lane >> 3) & 1;
    const int rmB = lane & 7;
    const uint32_t aRow  = (uint32_t)(wm * 32 + (lane & 15)) * 128;
    const uint32_t bRow  = (uint32_t)(wn * (NT * 8) + (lane & 7) +
                                      ((lane >> 4) & 1) * 8) * 128;
    const uint32_t bRow2 = (uint32_t)(wn * (NT * 8) + (NT - 1) * 8 +
                                      (lane & 7)) * 128;
#pragma unroll
    for (int kk = 0; kk < 4; ++kk) {
        const uint32_t sA = (uint32_t)(((kk * 2 + hi16) ^ rmA) << 4);
        const uint32_t sB = (uint32_t)(((kk * 2 + sbB) ^ rmB) << 4);
        uint32_t ah[2][4], al[2][4];
#pragma unroll
        for (int mt = 0; mt < 2; ++mt) {
            uint32_t off = aRow + mt * 2048 + sA;
            LDSM4(ah[mt], Ah + off);
            LDSM4(al[mt], Al + off);
        }
#pragma unroll
        for (int p = 0; p < NT / 2; ++p) {
            uint32_t off = bRow + p * 2048 + sB;
            uint32_t bh[4], bl[4];
            LDSM4(bh, Bh + off);
            LDSM4(bl, Bl + off);
#pragma unroll
            for (int q = 0; q < 2; ++q)
#pragma unroll
                for (int mt = 0; mt < 2; ++mt) {
                    mma16816(acc[mt][p * 2 + q], ah[mt], bh + q * 2);
                    mma16816(acc[mt][p * 2 + q], ah[mt], bl + q * 2);
                    mma16816(acc[mt][p * 2 + q], al[mt], bh + q * 2);
                }
        }
        if (NT & 1) {
            uint32_t off = bRow2 + sB;
            uint32_t bh[2], bl[2];
            LDSM2(bh, Bh + off);
            LDSM2(bl, Bl + off);
#pragma unroll
            for (int mt = 0; mt < 2; ++mt) {
                mma16816(acc[mt][NT - 1], ah[mt], bh);
                mma16816(acc[mt][NT - 1], ah[mt], bl);
                mma16816(acc[mt][NT - 1], al[mt], bh);
            }
        }
    }
}

// ------------------------- prep kernels ------------------------------------
__global__ void prep_x(const float* __restrict__ x) {
    int idx = blockIdx.x * 256 + threadIdx.x;
    if (idx >= 32 * 5 * 528 * 64) return;
    int j = idx & 63;
    int rest = idx >> 6;
    int r = rest % 528; rest /= 528;
    int kc = rest % 5;
    int b = rest / 5;
    int rr = r - 8; rr = rr < 0 ? 0 : (rr > 511 ? 511 : rr);
    int c = kc * 64 + j;
    float v = (c < 300) ? x[((size_t)(b * 512 + rr)) * 300 + c] : 0.f;
    __nv_bfloat16 h = __float2bfloat16(v);
    int pir = (((j >> 3) ^ (r & 7)) << 3) | (j & 7);
    size_t e = ((size_t)((b * 5 + kc) * 528 + r)) * 64 + pir;
    g_xch[e] = h;
    g_xcl[e] = __float2bfloat16(v - __bfloat162float(h));
}

__global__ void prep_wc(const float* __restrict__ w1, const float* __restrict__ w2,
                        const float* __restrict__ w3, const float* __restrict__ w7) {
    int idx = blockIdx.x * 256 + threadIdx.x;
    if (idx >= 65 * 320 * 64) return;
    int j = idx & 63;
    int oc = (idx >> 6) % 320;
    int s = (idx >> 6) / 320;
    int conv = (s < 5) ? 0 : (s < 15) ? 1 : (s < 30) ? 2 : 3;
    int sb = (conv == 0) ? 0 : (conv == 1) ? 5 : (conv == 2) ? 15 : 30;
    int rel = s - sb;
    int tap = rel / 5, kc = rel % 5;
    int ic = kc * 64 + j;
    float v = 0.f;
    if (oc < 300 && ic < 300) {
        if (conv == 0)      v = w1[(oc * 300 + ic)];
        else if (conv == 1) v = w2[(oc * 300 + ic) * 2 + tap];
        else if (conv == 2) v = w3[(oc * 300 + ic) * 3 + tap];
        else                v = w7[(oc * 300 + ic) * 7 + tap];
    }
    __nv_bfloat16 h = __float2bfloat16(v);
    int pir = (((j >> 3) ^ (oc & 7)) << 3) | (j & 7);
    size_t e = ((size_t)(s * 320 + oc)) * 64 + pir;
    g_wcch[e] = h;
    g_wccl[e] = __float2bfloat16(v - __bfloat162float(h));
}

__global__ void prep_we(const float* __restrict__ slp_w,
                        const float* __restrict__ b1, const float* __restrict__ b2,
                        const float* __restrict__ b3, const float* __restrict__ b7) {
    int idx = blockIdx.x * 256 + threadIdx.x;
    if (idx < 19 * 512 * 64) {
        int j = idx & 63;
        int oc = (idx >> 6) & 511;
        int kc = idx >> 15;
        int ic = kc * 64 + j;
        float v = 0.f;
        if (ic < 600)       v = slp_w[oc * 1500 + ic];
        else if (ic < 900)  v = slp_w[oc * 1500 + ic] + slp_w[oc * 1500 + ic + 300];
        else if (ic < 1200) v = slp_w[oc * 1500 + ic + 300];
        __nv_bfloat16 h = __float2bfloat16(v);
        int pir = (((j >> 3) ^ (oc & 7)) << 3) | (j & 7);
        size_t e = ((size_t)(kc * 512 + oc)) * 64 + pir;
        g_wech[e] = h;
        g_wecl[e] = __float2bfloat16(v - __bfloat162float(h));
    }
    if (idx < 1200) {
        int conv = idx / 300, oc = idx % 300;
        const float* b = (conv == 0) ? b1 : (conv == 1) ? b2 : (conv == 2) ? b3 : b7;
        g_bconv[idx] = b[oc];
    }
}

// ------------------------- conv GEMM kernel (BM=128, BN=160) ---------------
__global__ __launch_bounds__(512, 1)
void conv_mma_kernel() {
    extern __shared__ char sm[];
    const uint32_t smb = smem_u32(sm);
    const uint32_t mb0 = smb + 2 * CH_BUF;
    const int tid = threadIdx.x, lane = tid & 31, wid = tid >> 5;
    const int wm = wid & 3, wn = wid >> 2;
    const int quad = lane >> 2, kp2 = (lane & 3) * 2;

    const int conv = 3 - (int)(blockIdx.x >> 1);  // long convs first
    const int oc0  = (blockIdx.x & 1) * 160;
    const int pos0 = blockIdx.y * 128;
    const int bat = pos0 >> 9, l0 = pos0 & 511;
    const int nc = c_nch[conv];
    const int sbase = c_sb[conv];
    const int tb = c_base[conv];

    if (tid == 0) { MBAR_INIT(mb0, 1); MBAR_INIT(mb0 + 8, 1); }
    __syncthreads();

    float acc[2][5][4];
#pragma unroll
    for (int mt = 0; mt < 2; ++mt)
#pragma unroll
        for (int nt = 0; nt < 5; ++nt)
#pragma unroll
            for (int e = 0; e < 4; ++e) acc[mt][nt][e] = 0.f;

    auto issue = [&](int ch, int buf) {  // thread 0 only
        int tap = ch / 5, kc = ch - tap * 5;
        int dlt = c_off[tb + tap];
        const char* ah = (const char*)g_xch +
            ((size_t)((bat * 5 + kc) * 528 + 8 + l0 + dlt)) * 128;
        const char* al = (const char*)g_xcl +
            ((size_t)((bat * 5 + kc) * 528 + 8 + l0 + dlt)) * 128;
        const char* bh = (const char*)g_wcch +
            ((size_t)((sbase + ch) * 320 + oc0)) * 128;
        const char* bl = (const char*)g_wccl +
            ((size_t)((sbase + ch) * 320 + oc0)) * 128;
        uint32_t d = smb + buf * CH_BUF;
        uint32_t m = mb0 + buf * 8;
        MBAR_EXPECT_TX(m, CH_BUF);
        BULK_G2S(d + CH_A_H, ah, 16384, m);
        BULK_G2S(d + CH_A_L, al, 16384, m);
        BULK_G2S(d + CH_B_H, bh, 20480, m);
        BULK_G2S(d + CH_B_L, bl, 20480, m);
    };

    if (tid == 0) { issue(0, 0); issue(1, 1); }

    int ph0 = 0, ph1 = 0;
    for (int ch = 0; ch < nc; ++ch) {
        int buf = ch & 1;
        if (buf == 0) { mbar_wait(mb0, ph0); ph0 ^= 1; }
        else          { mbar_wait(mb0 + 8, ph1); ph1 ^= 1; }
        int tap = ch / 5;
        int adj = (8 + c_off[tb + tap]) & 7;       // A swizzle phase
        int rmA = ((lane & 15) + adj) & 7;
        uint32_t d = smb + buf * CH_BUF;
        compute_buf<5>(d + CH_A_H, d + CH_A_L, d + CH_B_H, d + CH_B_L,
                       acc, wm, wn, lane, rmA);
        __syncthreads();
        if (tid == 0 && ch + 2 < nc) issue(ch + 2, buf);
    }

    // epilogue: tanh(acc + bias) -> chunked+swizzled hi/lo h
#pragma unroll
    for (int mt = 0; mt < 2; ++mt) {
        int r0 = pos0 + wm * 32 + mt * 16 + quad;
#pragma unroll
        for (int nt = 0; nt < 5; ++nt) {
            int col = oc0 + wn * 40 + nt * 8 + kp2;
            if (col >= 300) continue;
            int gc = conv * 300 + col;
            int kc = gc >> 6, j = gc & 63;
            float bi0 = g_bconv[gc], bi1 = g_bconv[gc + 1];
#pragma unroll
            for (int half = 0; half < 2; ++half) {
                int r = r0 + half * 8;
                float v0 = tanhf(acc[mt][nt][half * 2 + 0] + bi0);
                float v1 = tanhf(acc[mt][nt][half * 2 + 1] + bi1);
                __nv_bfloat16 h0 = __float2bfloat16(v0);
                __nv_bfloat16 h1 = __float2bfloat16(v1);
                __nv_bfloat162 hv; hv.x = h0; hv.y = h1;
                __nv_bfloat162 lv;
                lv.x = __float2bfloat16(v0 - __bfloat162float(h0));
                lv.y = __float2bfloat16(v1 - __bfloat162float(h1));
                int pir = (((j >> 3) ^ (r & 7)) << 3) | (j & 7);
                size_t e = ((size_t)kc * 16384 + r) * 64 + pir;
                *(__nv_bfloat162*)(g_hch + e) = hv;
                *(__nv_bfloat162*)(g_hcl + e) = lv;
            }
        }
    }
}

// ------------------------- SLP GEMM kernel (BM=128, BN=128) ----------------
__global__ __launch_bounds__(512, 1)
void slp_mma_kernel(const float* __restrict__ slp_b, float* __restrict__ out) {
    extern __shared__ char sm[];
    const uint32_t smb = smem_u32(sm);
    const uint32_t mb0 = smb + 2 * SL_BUF;
    const int tid = threadIdx.x, lane = tid & 31, wid = tid >> 5;
    const int wm = wid & 3, wn = wid >> 2;
    const int quad = lane >> 2, kp2 = (lane & 3) * 2;
    const int oc0  = blockIdx.x * 128;
    const int pos0 = blockIdx.y * 128;
    const int nc = 19;
    const int rmA = lane & 7;

    if (tid == 0) { MBAR_INIT(mb0, 1); MBAR_INIT(mb0 + 8, 1); }
    __syncthreads();

    float acc[2][4][4];
#pragma unroll
    for (int mt = 0; mt < 2; ++mt)
#pragma unroll
        for (int nt = 0; nt < 4; ++nt)
#pragma unroll
            for (int e = 0; e < 4; ++e) acc[mt][nt][e] = 0.f;

    auto issue = [&](int ch, int buf) {
        const char* ah = (const char*)g_hch + ((size_t)ch * 16384 + pos0) * 128;
        const char* al = (const char*)g_hcl + ((size_t)ch * 16384 + pos0) * 128;
        const char* bh = (const char*)g_wech + ((size_t)ch * 512 + oc0) * 128;
        const char* bl = (const char*)g_wecl + ((size_t)ch * 512 + oc0) * 128;
        uint32_t d = smb + buf * SL_BUF;
        uint32_t m = mb0 + buf * 8;
        MBAR_EXPECT_TX(m, SL_BUF);
        BULK_G2S(d + SL_A_H, ah, 16384, m);
        BULK_G2S(d + SL_A_L, al, 16384, m);
        BULK_G2S(d + SL_B_H, bh, 16384, m);
        BULK_G2S(d + SL_B_L, bl, 16384, m);
    };

    if (tid == 0) { issue(0, 0); issue(1, 1); }

    int ph0 = 0, ph1 = 0;
    for (int ch = 0; ch < nc; ++ch) {
        int buf = ch & 1;
        if (buf == 0) { mbar_wait(mb0, ph0); ph0 ^= 1; }
        else          { mbar_wait(mb0 + 8, ph1); ph1 ^= 1; }
        uint32_t d = smb + buf * SL_BUF;
        compute_buf<4>(d + SL_A_H, d + SL_A_L, d + SL_B_H, d + SL_B_L,
                       acc, wm, wn, lane, rmA);
        __syncthreads();
        if (tid == 0 && ch + 2 < nc) issue(ch + 2, buf);
    }

#pragma unroll
    for (int mt = 0; mt < 2; ++mt) {
        int r0 = pos0 + wm * 32 + mt * 16 + quad;
#pragma unroll
        for (int nt = 0; nt < 4; ++nt) {
            int col = oc0 + wn * 32 + nt * 8 + kp2;
            float bi0 = slp_b[col], bi1 = slp_b[col + 1];
#pragma unroll
            for (int half = 0; half < 2; ++half) {
                int r = r0 + half * 8;
                float2 v;
                v.x = tanhf(acc[mt][nt][half * 2 + 0] + bi0);
                v.y = tanhf(acc[mt][nt][half * 2 + 1] + bi1);
                *(float2*)(out + (size_t)r * 512 + col) = v;
            }
        }
    }
}

// ------------------------- launch ------------------------------------------
extern "C" void kernel_launch(void* const* d_in, const int* in_sizes, int n_in,
                              void* d_out, int out_size) {
    const float* x     = (const float*)d_in[0];
    const float* w1    = (const float*)d_in[1];
    const float* b1    = (const float*)d_in[2];
    const float* w2    = (const float*)d_in[3];
    const float* b2    = (const float*)d_in[4];
    const float* w3    = (const float*)d_in[5];
    const float* b3    = (const float*)d_in[6];
    const float* w7    = (const float*)d_in[7];
    const float* b7    = (const float*)d_in[8];
    const float* slp_w = (const float*)d_in[9];
    const float* slp_b = (const float*)d_in[10];
    float* out = (float*)d_out;

    cudaFuncSetAttribute(conv_mma_kernel, cudaFuncAttributeMaxDynamicSharedMemorySize, CONV_SMEM);
    cudaFuncSetAttribute(slp_mma_kernel,  cudaFuncAttributeMaxDynamicSharedMemorySize, SLP_SMEM);

    prep_x<<<(32 * 5 * 528 * 64 + 255) / 256, 256>>>(x);
    prep_wc<<<(65 * 320 * 64 + 255) / 256, 256>>>(w1, w2, w3, w7);
    prep_we<<<(19 * 512 * 64 + 255) / 256, 256>>>(slp_w, b1, b2, b3, b7);

    conv_mma_kernel<<<dim3(8, 128), 512, CONV_SMEM>>>();
    slp_mma_kernel<<<dim3(4, 128), 512, SLP_SMEM>>>(slp_b, out);
}

// round 6
// speedup vs baseline: 6.8404x; 2.0998x over previous
#include <cuda_runtime.h>
#include <cuda_fp16.h>
#include <math.h>
#include <stdint.h>

// ===========================================================================
// TxtNet, single-term fp16 HMMA.16816 (fp32 accum) fed by cp.async.bulk.
// fp16 (11-bit mantissa) keeps final rel_err ~5e-4 < 1e-3, so the 3-term
// bf16 split is dropped: 3x less MMA work, half the SMEM traffic.
// Chunk-major pre-swizzled GMEM layouts (prep kernels); 4-deep bulk pipeline.
// Conv: 4 GEMMs, K=ntap*320 (tap shift baked into guarded x slabs).
// SLP:  16384 x 1216 x 512 with the x5==x3 fold.
// ===========================================================================

#define P_TOT 16384

// conv smem: A 16K + B 20K per buffer, 4 buffers
#define CH_A 0
#define CH_B 16384
#define CH_BUF 36864
#define CONV_SMEM (4 * CH_BUF + 64)
// slp smem: A 16K + B 16K per buffer, 4 buffers
#define SL_A 0
#define SL_B 16384
#define SL_BUF 32768
#define SLP_SMEM (4 * SL_BUF + 64)

// ------------------------- device scratch (zero-init) ----------------------
// x chunked: [b 32][kc 5][row 528 (8 guard each side)][64], swizzled by row&7
__device__ __half g_xc[32 * 5 * 528 * 64];
// conv weights chunked: [s 65][oc 320][64], swizzled by oc&7
__device__ __half g_wcc[65 * 320 * 64];
// h chunked: [kc 19][pos 16384][64], swizzled by pos&7 (cols 1200+ stay zero)
__device__ __half g_hc[19 * 16384 * 64];
// slp weights chunked: [kc 19][oc 512][64], swizzled by oc&7
__device__ __half g_wec[19 * 512 * 64];
__device__ float g_bconv[1200];

__constant__ int c_off[13] = {0,  0, 1,  -1, 0, 1,  -3, -2, -1, 0, 1, 2, 3};
__constant__ int c_base[4] = {0, 1, 3, 6};
__constant__ int c_nch[4]  = {5, 10, 15, 35};   // chunks per conv
__constant__ int c_sb[4]   = {0, 5, 15, 30};    // chunk-slab base per conv

// ------------------------- asm helpers -------------------------------------
__device__ __forceinline__ uint32_t smem_u32(const void* p) {
    uint32_t a;
    asm("{ .reg .u64 t; cvta.to.shared.u64 t, %1; cvt.u32.u64 %0, t; }"
        : "=r"(a) : "l"(p));
    return a;
}
#define BULK_G2S(dst, src, bytes, mbar)                                        \
    asm volatile(                                                              \
        "cp.async.bulk.shared::cluster.global.mbarrier::complete_tx::bytes "   \
        "[%0], [%1], %2, [%3];"                                                \
        :: "r"(dst), "l"(src), "r"(bytes), "r"(mbar) : "memory")
#define MBAR_INIT(a, c) \
    asm volatile("mbarrier.init.shared.b64 [%0], %1;" :: "r"(a), "r"(c) : "memory")
#define MBAR_EXPECT_TX(a, b) \
    asm volatile("mbarrier.arrive.expect_tx.shared.b64 _, [%0], %1;" \
                 :: "r"(a), "r"(b) : "memory")
__device__ __forceinline__ void mbar_wait(uint32_t a, uint32_t ph) {
    asm volatile(
        "{\n .reg .pred P;\nW%=:\n"
        " mbarrier.try_wait.parity.acquire.cta.shared::cta.b64 P, [%0], %1, 0x989680;\n"
        " @!P bra W%=;\n}"
        :: "r"(a), "r"(ph) : "memory");
}
#define LDSM4(R, A) \
    asm volatile("ldmatrix.sync.aligned.m8n8.x4.shared.b16 {%0,%1,%2,%3}, [%4];" \
                 : "=r"((R)[0]), "=r"((R)[1]), "=r"((R)[2]), "=r"((R)[3]) : "r"(A))
#define LDSM2(R, A) \
    asm volatile("ldmatrix.sync.aligned.m8n8.x2.shared.b16 {%0,%1}, [%2];" \
                 : "=r"((R)[0]), "=r"((R)[1]) : "r"(A))

__device__ __forceinline__ void mma16816(float* d, const uint32_t* a,
                                         const uint32_t* b) {
    asm volatile(
        "mma.sync.aligned.m16n8k16.row.col.f32.f16.f16.f32 "
        "{%0,%1,%2,%3}, {%4,%5,%6,%7}, {%8,%9}, {%0,%1,%2,%3};"
        : "+f"(d[0]), "+f"(d[1]), "+f"(d[2]), "+f"(d[3])
        : "r"(a[0]), "r"(a[1]), "r"(a[2]), "r"(a[3]), "r"(b[0]), "r"(b[1]));
}

// ------------------------- core compute ------------------------------------
// SMEM tiles: 128B row stride, SW128 pre-baked in GMEM. rmA = per-lane A
// swizzle phase; B phase = lane&7 (tiles start 8-row aligned).
template <int NT>
__device__ __forceinline__ void compute_buf(uint32_t Ah, uint32_t Bh,
                                            float (&acc)[2][NT][4],
                                            int wm, int wn, int lane, int rmA) {
    const int hi16 = lane >> 4;
    const int sbB = (lane >> 3) & 1;
    const int rmB = lane & 7;
    const uint32_t aRow  = (uint32_t)(wm * 32 + (lane & 15)) * 128;
    const uint32_t bRow  = (uint32_t)(wn * (NT * 8) + (lane & 7) +
                                      ((lane >> 4) & 1) * 8) * 128;
    const uint32_t bRow2 = (uint32_t)(wn * (NT * 8) + (NT - 1) * 8 +
                                      (lane & 7)) * 128;
#pragma unroll
    for (int kk = 0; kk < 4; ++kk) {
        const uint32_t sA = (uint32_t)(((kk * 2 + hi16) ^ rmA) << 4);
        const uint32_t sB = (uint32_t)(((kk * 2 + sbB) ^ rmB) << 4);
        uint32_t ah[2][4];
#pragma unroll
        for (int mt = 0; mt < 2; ++mt) {
            LDSM4(ah[mt], Ah + aRow + mt * 2048 + sA);
        }
#pragma unroll
        for (int p = 0; p < NT / 2; ++p) {
            uint32_t bh[4];
            LDSM4(bh, Bh + bRow + p * 2048 + sB);
#pragma unroll
            for (int q = 0; q < 2; ++q)
#pragma unroll
                for (int mt = 0; mt < 2; ++mt)
                    mma16816(acc[mt][p * 2 + q], ah[mt], bh + q * 2);
        }
        if (NT & 1) {
            uint32_t bh[2];
            LDSM2(bh, Bh + bRow2 + sB);
#pragma unroll
            for (int mt = 0; mt < 2; ++mt)
                mma16816(acc[mt][NT - 1], ah[mt], bh);
        }
    }
}

// ------------------------- prep kernels ------------------------------------
__global__ void prep_x(const float* __restrict__ x) {
    int idx = blockIdx.x * 256 + threadIdx.x;
    if (idx >= 32 * 5 * 528 * 64) return;
    int j = idx & 63;
    int rest = idx >> 6;
    int r = rest % 528; rest /= 528;
    int kc = rest % 5;
    int b = rest / 5;
    int rr = r - 8; rr = rr < 0 ? 0 : (rr > 511 ? 511 : rr);
    int c = kc * 64 + j;
    float v = (c < 300) ? x[((size_t)(b * 512 + rr)) * 300 + c] : 0.f;
    int pir = (((j >> 3) ^ (r & 7)) << 3) | (j & 7);
    g_xc[((size_t)((b * 5 + kc) * 528 + r)) * 64 + pir] = __float2half_rn(v);
}

__global__ void prep_wc(const float* __restrict__ w1, const float* __restrict__ w2,
                        const float* __restrict__ w3, const float* __restrict__ w7) {
    int idx = blockIdx.x * 256 + threadIdx.x;
    if (idx >= 65 * 320 * 64) return;
    int j = idx & 63;
    int oc = (idx >> 6) % 320;
    int s = (idx >> 6) / 320;
    int conv = (s < 5) ? 0 : (s < 15) ? 1 : (s < 30) ? 2 : 3;
    int sb = (conv == 0) ? 0 : (conv == 1) ? 5 : (conv == 2) ? 15 : 30;
    int rel = s - sb;
    int tap = rel / 5, kc = rel % 5;
    int ic = kc * 64 + j;
    float v = 0.f;
    if (oc < 300 && ic < 300) {
        if (conv == 0)      v = w1[(oc * 300 + ic)];
        else if (conv == 1) v = w2[(oc * 300 + ic) * 2 + tap];
        else if (conv == 2) v = w3[(oc * 300 + ic) * 3 + tap];
        else                v = w7[(oc * 300 + ic) * 7 + tap];
    }
    int pir = (((j >> 3) ^ (oc & 7)) << 3) | (j & 7);
    g_wcc[((size_t)(s * 320 + oc)) * 64 + pir] = __float2half_rn(v);
}

__global__ void prep_we(const float* __restrict__ slp_w,
                        const float* __restrict__ b1, const float* __restrict__ b2,
                        const float* __restrict__ b3, const float* __restrict__ b7) {
    int idx = blockIdx.x * 256 + threadIdx.x;
    if (idx < 19 * 512 * 64) {
        int j = idx & 63;
        int oc = (idx >> 6) & 511;
        int kc = idx >> 15;
        int ic = kc * 64 + j;
        float v = 0.f;
        if (ic < 600)       v = slp_w[oc * 1500 + ic];
        else if (ic < 900)  v = slp_w[oc * 1500 + ic] + slp_w[oc * 1500 + ic + 300];
        else if (ic < 1200) v = slp_w[oc * 1500 + ic + 300];
        int pir = (((j >> 3) ^ (oc & 7)) << 3) | (j & 7);
        g_wec[((size_t)(kc * 512 + oc)) * 64 + pir] = __float2half_rn(v);
    }
    if (idx < 1200) {
        int conv = idx / 300, oc = idx % 300;
        const float* b = (conv == 0) ? b1 : (conv == 1) ? b2 : (conv == 2) ? b3 : b7;
        g_bconv[idx] = b[oc];
    }
}

// ------------------------- conv GEMM kernel (BM=128, BN=160) ---------------
__global__ __launch_bounds__(512, 1)
void conv_mma_kernel() {
    extern __shared__ char sm[];
    const uint32_t smb = smem_u32(sm);
    const uint32_t mb0 = smb + 4 * CH_BUF;
    const int tid = threadIdx.x, lane = tid & 31, wid = tid >> 5;
    const int wm = wid & 3, wn = wid >> 2;
    const int quad = lane >> 2, kp2 = (lane & 3) * 2;

    const int conv = 3 - (int)(blockIdx.x >> 1);  // long convs first
    const int oc0  = (blockIdx.x & 1) * 160;
    const int pos0 = blockIdx.y * 128;
    const int bat = pos0 >> 9, l0 = pos0 & 511;
    const int nc = c_nch[conv];
    const int sbase = c_sb[conv];
    const int tb = c_base[conv];

    if (tid == 0) {
#pragma unroll
        for (int i = 0; i < 4; ++i) MBAR_INIT(mb0 + i * 8, 1);
    }
    __syncthreads();

    float acc[2][5][4];
#pragma unroll
    for (int mt = 0; mt < 2; ++mt)
#pragma unroll
        for (int nt = 0; nt < 5; ++nt)
#pragma unroll
            for (int e = 0; e < 4; ++e) acc[mt][nt][e] = 0.f;

    auto issue = [&](int ch, int buf) {  // thread 0 only
        int tap = ch / 5, kc = ch - tap * 5;
        int dlt = c_off[tb + tap];
        const char* a = (const char*)g_xc +
            ((size_t)((bat * 5 + kc) * 528 + 8 + l0 + dlt)) * 128;
        const char* b = (const char*)g_wcc +
            ((size_t)((sbase + ch) * 320 + oc0)) * 128;
        uint32_t d = smb + buf * CH_BUF;
        uint32_t m = mb0 + buf * 8;
        MBAR_EXPECT_TX(m, CH_BUF);
        BULK_G2S(d + CH_A, a, 16384, m);
        BULK_G2S(d + CH_B, b, 20480, m);
    };

    if (tid == 0) {
        issue(0, 0);
        if (nc > 1) issue(1, 1);
        if (nc > 2) issue(2, 2);
    }

    for (int ch = 0; ch < nc; ++ch) {
        int buf = ch & 3;
        mbar_wait(mb0 + buf * 8, (ch >> 2) & 1);
        int tap = ch / 5;
        int adj = (8 + c_off[tb + tap]) & 7;       // A swizzle phase
        int rmA = ((lane & 15) + adj) & 7;
        uint32_t d = smb + buf * CH_BUF;
        compute_buf<5>(d + CH_A, d + CH_B, acc, wm, wn, lane, rmA);
        __syncthreads();
        if (tid == 0 && ch + 3 < nc) issue(ch + 3, (ch + 3) & 3);
    }

    // epilogue: tanh(acc + bias) -> chunked+swizzled fp16 h
#pragma unroll
    for (int mt = 0; mt < 2; ++mt) {
        int r0 = pos0 + wm * 32 + mt * 16 + quad;
#pragma unroll
        for (int nt = 0; nt < 5; ++nt) {
            int col = oc0 + wn * 40 + nt * 8 + kp2;
            if (col >= 300) continue;
            int gc = conv * 300 + col;
            int kc = gc >> 6, j = gc & 63;
            float bi0 = g_bconv[gc], bi1 = g_bconv[gc + 1];
#pragma unroll
            for (int half = 0; half < 2; ++half) {
                int r = r0 + half * 8;
                __half2 hv;
                hv.x = __float2half_rn(tanhf(acc[mt][nt][half * 2 + 0] + bi0));
                hv.y = __float2half_rn(tanhf(acc[mt][nt][half * 2 + 1] + bi1));
                int pir = (((j >> 3) ^ (r & 7)) << 3) | (j & 7);
                *(__half2*)(g_hc + ((size_t)kc * 16384 + r) * 64 + pir) = hv;
            }
        }
    }
}

// ------------------------- SLP GEMM kernel (BM=128, BN=128) ----------------
__global__ __launch_bounds__(512, 1)
void slp_mma_kernel(const float* __restrict__ slp_b, float* __restrict__ out) {
    extern __shared__ char sm[];
    const uint32_t smb = smem_u32(sm);
    const uint32_t mb0 = smb + 4 * SL_BUF;
    const int tid = threadIdx.x, lane = tid & 31, wid = tid >> 5;
    const int wm = wid & 3, wn = wid >> 2;
    const int quad = lane >> 2, kp2 = (lane & 3) * 2;
    const int oc0  = blockIdx.x * 128;
    const int pos0 = blockIdx.y * 128;
    const int nc = 19;
    const int rmA = lane & 7;

    if (tid == 0) {
#pragma unroll
        for (int i = 0; i < 4; ++i) MBAR_INIT(mb0 + i * 8, 1);
    }
    __syncthreads();

    float acc[2][4][4];
#pragma unroll
    for (int mt = 0; mt < 2; ++mt)
#pragma unroll
        for (int nt = 0; nt < 4; ++nt)
#pragma unroll
            for (int e = 0; e < 4; ++e) acc[mt][nt][e] = 0.f;

    auto issue = [&](int ch, int buf) {
        const char* a = (const char*)g_hc + ((size_t)ch * 16384 + pos0) * 128;
        const char* b = (const char*)g_wec + ((size_t)ch * 512 + oc0) * 128;
        uint32_t d = smb + buf * SL_BUF;
        uint32_t m = mb0 + buf * 8;
        MBAR_EXPECT_TX(m, SL_BUF);
        BULK_G2S(d + SL_A, a, 16384, m);
        BULK_G2S(d + SL_B, b, 16384, m);
    };

    if (tid == 0) { issue(0, 0); issue(1, 1); issue(2, 2); }

    for (int ch = 0; ch < nc; ++ch) {
        int buf = ch & 3;
        mbar_wait(mb0 + buf * 8, (ch >> 2) & 1);
        uint32_t d = smb + buf * SL_BUF;
        compute_buf<4>(d + SL_A, d + SL_B, acc, wm, wn, lane, rmA);
        __syncthreads();
        if (tid == 0 && ch + 3 < nc) issue(ch + 3, (ch + 3) & 3);
    }

#pragma unroll
    for (int mt = 0; mt < 2; ++mt) {
        int r0 = pos0 + wm * 32 + mt * 16 + quad;
#pragma unroll
        for (int nt = 0; nt < 4; ++nt) {
            int col = oc0 + wn * 32 + nt * 8 + kp2;
            float bi0 = slp_b[col], bi1 = slp_b[col + 1];
#pragma unroll
            for (int half = 0; half < 2; ++half) {
                int r = r0 + half * 8;
                float2 v;
                v.x = tanhf(acc[mt][nt][half * 2 + 0] + bi0);
                v.y = tanhf(acc[mt][nt][half * 2 + 1] + bi1);
                *(float2*)(out + (size_t)r * 512 + col) = v;
            }
        }
    }
}

// ------------------------- launch ------------------------------------------
extern "C" void kernel_launch(void* const* d_in, const int* in_sizes, int n_in,
                              void* d_out, int out_size) {
    const float* x     = (const float*)d_in[0];
    const float* w1    = (const float*)d_in[1];
    const float* b1    = (const float*)d_in[2];
    const float* w2    = (const float*)d_in[3];
    const float* b2    = (const float*)d_in[4];
    const float* w3    = (const float*)d_in[5];
    const float* b3    = (const float*)d_in[6];
    const float* w7    = (const float*)d_in[7];
    const float* b7    = (const float*)d_in[8];
    const float* slp_w = (const float*)d_in[9];
    const float* slp_b = (const float*)d_in[10];
    float* out = (float*)d_out;

    cudaFuncSetAttribute(conv_mma_kernel, cudaFuncAttributeMaxDynamicSharedMemorySize, CONV_SMEM);
    cudaFuncSetAttribute(slp_mma_kernel,  cudaFuncAttributeMaxDynamicSharedMemorySize, SLP_SMEM);

    prep_x<<<(32 * 5 * 528 * 64 + 255) / 256, 256>>>(x);
    prep_wc<<<(65 * 320 * 64 + 255) / 256, 256>>>(w1, w2, w3, w7);
    prep_we<<<(19 * 512 * 64 + 255) / 256, 256>>>(slp_w, b1, b2, b3, b7);

    conv_mma_kernel<<<dim3(8, 128), 512, CONV_SMEM>>>();
    slp_mma_kernel<<<dim3(4, 128), 512, SLP_SMEM>>>(slp_b, out);
}

// round 7
// speedup vs baseline: 7.8758x; 1.1514x over previous
#include <cuda_runtime.h>
#include <cuda_fp16.h>
#include <math.h>
#include <stdint.h>

// ===========================================================================
// TxtNet, single-term fp16 HMMA.16816 (fp32 accum) fed by cp.async.bulk.
// R7: per-chunk __syncthreads replaced by producer/consumer EMPTY mbarriers
// (arrive-count 16, one per warp); deeper pipelines (conv 5, slp 6 buffers).
// Chunk-major pre-swizzled GMEM layouts (prep kernels).
// Conv: 4 GEMMs, K=ntap*320 (tap shift baked into guarded x slabs).
// SLP:  16384 x 1216 x 512 with the x5==x3 fold.
// ===========================================================================

#define P_TOT 16384

// conv smem: A 16K + B 20K per buffer, 5 buffers
#define CH_A 0
#define CH_B 16384
#define CH_BUF 36864
#define C_NBUF 5
#define CONV_SMEM (C_NBUF * CH_BUF + 128)
// slp smem: A 16K + B 16K per buffer, 6 buffers
#define SL_A 0
#define SL_B 16384
#define SL_BUF 32768
#define S_NBUF 6
#define SLP_SMEM (S_NBUF * SL_BUF + 128)

// ------------------------- device scratch (zero-init) ----------------------
// x chunked: [b 32][kc 5][row 528 (8 guard each side)][64], swizzled by row&7
__device__ __half g_xc[32 * 5 * 528 * 64];
// conv weights chunked: [s 65][oc 320][64], swizzled by oc&7
__device__ __half g_wcc[65 * 320 * 64];
// h chunked: [kc 19][pos 16384][64], swizzled by pos&7 (cols 1200+ stay zero)
__device__ __half g_hc[19 * 16384 * 64];
// slp weights chunked: [kc 19][oc 512][64], swizzled by oc&7
__device__ __half g_wec[19 * 512 * 64];
__device__ float g_bconv[1200];

__constant__ int c_off[13] = {0,  0, 1,  -1, 0, 1,  -3, -2, -1, 0, 1, 2, 3};
__constant__ int c_base[4] = {0, 1, 3, 6};
__constant__ int c_nch[4]  = {5, 10, 15, 35};   // chunks per conv
__constant__ int c_sb[4]   = {0, 5, 15, 30};    // chunk-slab base per conv

// ------------------------- asm helpers -------------------------------------
__device__ __forceinline__ uint32_t smem_u32(const void* p) {
    uint32_t a;
    asm("{ .reg .u64 t; cvta.to.shared.u64 t, %1; cvt.u32.u64 %0, t; }"
        : "=r"(a) : "l"(p));
    return a;
}
#define BULK_G2S(dst, src, bytes, mbar)                                        \
    asm volatile(                                                              \
        "cp.async.bulk.shared::cluster.global.mbarrier::complete_tx::bytes "   \
        "[%0], [%1], %2, [%3];"                                                \
        :: "r"(dst), "l"(src), "r"(bytes), "r"(mbar) : "memory")
#define MBAR_INIT(a, c) \
    asm volatile("mbarrier.init.shared.b64 [%0], %1;" :: "r"(a), "r"(c) : "memory")
#define MBAR_EXPECT_TX(a, b) \
    asm volatile("mbarrier.arrive.expect_tx.shared.b64 _, [%0], %1;" \
                 :: "r"(a), "r"(b) : "memory")
#define MBAR_ARRIVE(a) \
    asm volatile("mbarrier.arrive.shared.b64 _, [%0];" :: "r"(a) : "memory")
#define FENCE_ASYNC() \
    asm volatile("fence.proxy.async.shared::cta;" ::: "memory")
__device__ __forceinline__ void mbar_wait(uint32_t a, uint32_t ph) {
    asm volatile(
        "{\n .reg .pred P;\nW%=:\n"
        " mbarrier.try_wait.parity.acquire.cta.shared::cta.b64 P, [%0], %1, 0x989680;\n"
        " @!P bra W%=;\n}"
        :: "r"(a), "r"(ph) : "memory");
}
#define LDSM4(R, A) \
    asm volatile("ldmatrix.sync.aligned.m8n8.x4.shared.b16 {%0,%1,%2,%3}, [%4];" \
                 : "=r"((R)[0]), "=r"((R)[1]), "=r"((R)[2]), "=r"((R)[3]) : "r"(A))
#define LDSM2(R, A) \
    asm volatile("ldmatrix.sync.aligned.m8n8.x2.shared.b16 {%0,%1}, [%2];" \
                 : "=r"((R)[0]), "=r"((R)[1]) : "r"(A))

__device__ __forceinline__ void mma16816(float* d, const uint32_t* a,
                                         const uint32_t* b) {
    asm volatile(
        "mma.sync.aligned.m16n8k16.row.col.f32.f16.f16.f32 "
        "{%0,%1,%2,%3}, {%4,%5,%6,%7}, {%8,%9}, {%0,%1,%2,%3};"
        : "+f"(d[0]), "+f"(d[1]), "+f"(d[2]), "+f"(d[3])
        : "r"(a[0]), "r"(a[1]), "r"(a[2]), "r"(a[3]), "r"(b[0]), "r"(b[1]));
}

// ------------------------- core compute ------------------------------------
template <int NT>
__device__ __forceinline__ void compute_buf(uint32_t Ah, uint32_t Bh,
                                            float (&acc)[2][NT][4],
                                            int wm, int wn, int lane, int rmA) {
    const int hi16 = lane >> 4;
    const int sbB = (lane >> 3) & 1;
    const int rmB = lane & 7;
    const uint32_t aRow  = (uint32_t)(wm * 32 + (lane & 15)) * 128;
    const uint32_t bRow  = (uint32_t)(wn * (NT * 8) + (lane & 7) +
                                      ((lane >> 4) & 1) * 8) * 128;
    const uint32_t bRow2 = (uint32_t)(wn * (NT * 8) + (NT - 1) * 8 +
                                      (lane & 7)) * 128;
#pragma unroll
    for (int kk = 0; kk < 4; ++kk) {
        const uint32_t sA = (uint32_t)(((kk * 2 + hi16) ^ rmA) << 4);
        const uint32_t sB = (uint32_t)(((kk * 2 + sbB) ^ rmB) << 4);
        uint32_t ah[2][4];
#pragma unroll
        for (int mt = 0; mt < 2; ++mt) {
            LDSM4(ah[mt], Ah + aRow + mt * 2048 + sA);
        }
#pragma unroll
        for (int p = 0; p < NT / 2; ++p) {
            uint32_t bh[4];
            LDSM4(bh, Bh + bRow + p * 2048 + sB);
#pragma unroll
            for (int q = 0; q < 2; ++q)
#pragma unroll
                for (int mt = 0; mt < 2; ++mt)
                    mma16816(acc[mt][p * 2 + q], ah[mt], bh + q * 2);
        }
        if (NT & 1) {
            uint32_t bh[2];
            LDSM2(bh, Bh + bRow2 + sB);
#pragma unroll
            for (int mt = 0; mt < 2; ++mt)
                mma16816(acc[mt][NT - 1], ah[mt], bh);
        }
    }
}

// ------------------------- prep kernels ------------------------------------
__global__ void prep_x(const float* __restrict__ x) {
    int idx = blockIdx.x * 256 + threadIdx.x;
    if (idx >= 32 * 5 * 528 * 64) return;
    int j = idx & 63;
    int rest = idx >> 6;
    int r = rest % 528; rest /= 528;
    int kc = rest % 5;
    int b = rest / 5;
    int rr = r - 8; rr = rr < 0 ? 0 : (rr > 511 ? 511 : rr);
    int c = kc * 64 + j;
    float v = (c < 300) ? x[((size_t)(b * 512 + rr)) * 300 + c] : 0.f;
    int pir = (((j >> 3) ^ (r & 7)) << 3) | (j & 7);
    g_xc[((size_t)((b * 5 + kc) * 528 + r)) * 64 + pir] = __float2half_rn(v);
}

__global__ void prep_wc(const float* __restrict__ w1, const float* __restrict__ w2,
                        const float* __restrict__ w3, const float* __restrict__ w7) {
    int idx = blockIdx.x * 256 + threadIdx.x;
    if (idx >= 65 * 320 * 64) return;
    int j = idx & 63;
    int oc = (idx >> 6) % 320;
    int s = (idx >> 6) / 320;
    int conv = (s < 5) ? 0 : (s < 15) ? 1 : (s < 30) ? 2 : 3;
    int sb = (conv == 0) ? 0 : (conv == 1) ? 5 : (conv == 2) ? 15 : 30;
    int rel = s - sb;
    int tap = rel / 5, kc = rel % 5;
    int ic = kc * 64 + j;
    float v = 0.f;
    if (oc < 300 && ic < 300) {
        if (conv == 0)      v = w1[(oc * 300 + ic)];
        else if (conv == 1) v = w2[(oc * 300 + ic) * 2 + tap];
        else if (conv == 2) v = w3[(oc * 300 + ic) * 3 + tap];
        else                v = w7[(oc * 300 + ic) * 7 + tap];
    }
    int pir = (((j >> 3) ^ (oc & 7)) << 3) | (j & 7);
    g_wcc[((size_t)(s * 320 + oc)) * 64 + pir] = __float2half_rn(v);
}

__global__ void prep_we(const float* __restrict__ slp_w,
                        const float* __restrict__ b1, const float* __restrict__ b2,
                        const float* __restrict__ b3, const float* __restrict__ b7) {
    int idx = blockIdx.x * 256 + threadIdx.x;
    if (idx < 19 * 512 * 64) {
        int j = idx & 63;
        int oc = (idx >> 6) & 511;
        int kc = idx >> 15;
        int ic = kc * 64 + j;
        float v = 0.f;
        if (ic < 600)       v = slp_w[oc * 1500 + ic];
        else if (ic < 900)  v = slp_w[oc * 1500 + ic] + slp_w[oc * 1500 + ic + 300];
        else if (ic < 1200) v = slp_w[oc * 1500 + ic + 300];
        int pir = (((j >> 3) ^ (oc & 7)) << 3) | (j & 7);
        g_wec[((size_t)(kc * 512 + oc)) * 64 + pir] = __float2half_rn(v);
    }
    if (idx < 1200) {
        int conv = idx / 300, oc = idx % 300;
        const float* b = (conv == 0) ? b1 : (conv == 1) ? b2 : (conv == 2) ? b3 : b7;
        g_bconv[idx] = b[oc];
    }
}

// ------------------------- conv GEMM kernel (BM=128, BN=160) ---------------
__global__ __launch_bounds__(512, 1)
void conv_mma_kernel() {
    extern __shared__ char sm[];
    const uint32_t smb = smem_u32(sm);
    const uint32_t mbF = smb + C_NBUF * CH_BUF;          // full barriers
    const uint32_t mbE = mbF + C_NBUF * 8;               // empty barriers
    const int tid = threadIdx.x, lane = tid & 31, wid = tid >> 5;
    const int wm = wid & 3, wn = wid >> 2;
    const int quad = lane >> 2, kp2 = (lane & 3) * 2;

    const int conv = 3 - (int)(blockIdx.x >> 1);  // long convs first
    const int oc0  = (blockIdx.x & 1) * 160;
    const int pos0 = blockIdx.y * 128;
    const int bat = pos0 >> 9, l0 = pos0 & 511;
    const int nc = c_nch[conv];
    const int sbase = c_sb[conv];
    const int tb = c_base[conv];

    if (tid == 0) {
#pragma unroll
        for (int i = 0; i < C_NBUF; ++i) {
            MBAR_INIT(mbF + i * 8, 1);
            MBAR_INIT(mbE + i * 8, 16);
        }
        FENCE_ASYNC();
    }
    __syncthreads();

    float acc[2][5][4];
#pragma unroll
    for (int mt = 0; mt < 2; ++mt)
#pragma unroll
        for (int nt = 0; nt < 5; ++nt)
#pragma unroll
            for (int e = 0; e < 4; ++e) acc[mt][nt][e] = 0.f;

    auto issue = [&](int ch, int buf) {  // thread 0 only
        int tap = ch / 5, kc = ch - tap * 5;
        int dlt = c_off[tb + tap];
        const char* a = (const char*)g_xc +
            ((size_t)((bat * 5 + kc) * 528 + 8 + l0 + dlt)) * 128;
        const char* b = (const char*)g_wcc +
            ((size_t)((sbase + ch) * 320 + oc0)) * 128;
        uint32_t d = smb + buf * CH_BUF;
        uint32_t m = mbF + buf * 8;
        MBAR_EXPECT_TX(m, CH_BUF);
        BULK_G2S(d + CH_A, a, 16384, m);
        BULK_G2S(d + CH_B, b, 20480, m);
    };

    if (tid == 0) {
#pragma unroll
        for (int i = 0; i < C_NBUF; ++i)
            if (i < nc) issue(i, i);
    }

    int buf = 0, ph = 0;
    for (int ch = 0; ch < nc; ++ch) {
        mbar_wait(mbF + buf * 8, ph);
        int tap = ch / 5;
        int adj = (8 + c_off[tb + tap]) & 7;       // A swizzle phase
        int rmA = ((lane & 15) + adj) & 7;
        uint32_t d = smb + buf * CH_BUF;
        compute_buf<5>(d + CH_A, d + CH_B, acc, wm, wn, lane, rmA);
        __syncwarp();
        if (lane == 0) MBAR_ARRIVE(mbE + buf * 8);
        if (tid == 0 && ch + C_NBUF < nc) {
            mbar_wait(mbE + buf * 8, ph);          // all 16 warps done with buf
            issue(ch + C_NBUF, buf);
        }
        if (++buf == C_NBUF) { buf = 0; ph ^= 1; }
    }

    // epilogue: tanh(acc + bias) -> chunked+swizzled fp16 h
#pragma unroll
    for (int mt = 0; mt < 2; ++mt) {
        int r0 = pos0 + wm * 32 + mt * 16 + quad;
#pragma unroll
        for (int nt = 0; nt < 5; ++nt) {
            int col = oc0 + wn * 40 + nt * 8 + kp2;
            if (col >= 300) continue;
            int gc = conv * 300 + col;
            int kc = gc >> 6, j = gc & 63;
            float bi0 = g_bconv[gc], bi1 = g_bconv[gc + 1];
#pragma unroll
            for (int half = 0; half < 2; ++half) {
                int r = r0 + half * 8;
                __half2 hv;
                hv.x = __float2half_rn(tanhf(acc[mt][nt][half * 2 + 0] + bi0));
                hv.y = __float2half_rn(tanhf(acc[mt][nt][half * 2 + 1] + bi1));
                int pir = (((j >> 3) ^ (r & 7)) << 3) | (j & 7);
                *(__half2*)(g_hc + ((size_t)kc * 16384 + r) * 64 + pir) = hv;
            }
        }
    }
}

// ------------------------- SLP GEMM kernel (BM=128, BN=128) ----------------
__global__ __launch_bounds__(512, 1)
void slp_mma_kernel(const float* __restrict__ slp_b, float* __restrict__ out) {
    extern __shared__ char sm[];
    const uint32_t smb = smem_u32(sm);
    const uint32_t mbF = smb + S_NBUF * SL_BUF;
    const uint32_t mbE = mbF + S_NBUF * 8;
    const int tid = threadIdx.x, lane = tid & 31, wid = tid >> 5;
    const int wm = wid & 3, wn = wid >> 2;
    const int quad = lane >> 2, kp2 = (lane & 3) * 2;
    const int oc0  = blockIdx.x * 128;
    const int pos0 = blockIdx.y * 128;
    const int nc = 19;
    const int rmA = lane & 7;

    if (tid == 0) {
#pragma unroll
        for (int i = 0; i < S_NBUF; ++i) {
            MBAR_INIT(mbF + i * 8, 1);
            MBAR_INIT(mbE + i * 8, 16);
        }
        FENCE_ASYNC();
    }
    __syncthreads();

    float acc[2][4][4];
#pragma unroll
    for (int mt = 0; mt < 2; ++mt)
#pragma unroll
        for (int nt = 0; nt < 4; ++nt)
#pragma unroll
            for (int e = 0; e < 4; ++e) acc[mt][nt][e] = 0.f;

    auto issue = [&](int ch, int buf) {
        const char* a = (const char*)g_hc + ((size_t)ch * 16384 + pos0) * 128;
        const char* b = (const char*)g_wec + ((size_t)ch * 512 + oc0) * 128;
        uint32_t d = smb + buf * SL_BUF;
        uint32_t m = mbF + buf * 8;
        MBAR_EXPECT_TX(m, SL_BUF);
        BULK_G2S(d + SL_A, a, 16384, m);
        BULK_G2S(d + SL_B, b, 16384, m);
    };

    if (tid == 0) {
#pragma unroll
        for (int i = 0; i < S_NBUF; ++i)
            if (i < nc) issue(i, i);
    }

    int buf = 0, ph = 0;
    for (int ch = 0; ch < nc; ++ch) {
        mbar_wait(mbF + buf * 8, ph);
        uint32_t d = smb + buf * SL_BUF;
        compute_buf<4>(d + SL_A, d + SL_B, acc, wm, wn, lane, rmA);
        __syncwarp();
        if (lane == 0) MBAR_ARRIVE(mbE + buf * 8);
        if (tid == 0 && ch + S_NBUF < nc) {
            mbar_wait(mbE + buf * 8, ph);
            issue(ch + S_NBUF, buf);
        }
        if (++buf == S_NBUF) { buf = 0; ph ^= 1; }
    }

#pragma unroll
    for (int mt = 0; mt < 2; ++mt) {
        int r0 = pos0 + wm * 32 + mt * 16 + quad;
#pragma unroll
        for (int nt = 0; nt < 4; ++nt) {
            int col = oc0 + wn * 32 + nt * 8 + kp2;
            float bi0 = slp_b[col], bi1 = slp_b[col + 1];
#pragma unroll
            for (int half = 0; half < 2; ++half) {
                int r = r0 + half * 8;
                float2 v;
                v.x = tanhf(acc[mt][nt][half * 2 + 0] + bi0);
                v.y = tanhf(acc[mt][nt][half * 2 + 1] + bi1);
                *(float2*)(out + (size_t)r * 512 + col) = v;
            }
        }
    }
}

// ------------------------- launch ------------------------------------------
extern "C" void kernel_launch(void* const* d_in, const int* in_sizes, int n_in,
                              void* d_out, int out_size) {
    const float* x     = (const float*)d_in[0];
    const float* w1    = (const float*)d_in[1];
    const float* b1    = (const float*)d_in[2];
    const float* w2    = (const float*)d_in[3];
    const float* b2    = (const float*)d_in[4];
    const float* w3    = (const float*)d_in[5];
    const float* b3    = (const float*)d_in[6];
    const float* w7    = (const float*)d_in[7];
    const float* b7    = (const float*)d_in[8];
    const float* slp_w = (const float*)d_in[9];
    const float* slp_b = (const float*)d_in[10];
    float* out = (float*)d_out;

    cudaFuncSetAttribute(conv_mma_kernel, cudaFuncAttributeMaxDynamicSharedMemorySize, CONV_SMEM);
    cudaFuncSetAttribute(slp_mma_kernel,  cudaFuncAttributeMaxDynamicSharedMemorySize, SLP_SMEM);

    prep_x<<<(32 * 5 * 528 * 64 + 255) / 256, 256>>>(x);
    prep_wc<<<(65 * 320 * 64 + 255) / 256, 256>>>(w1, w2, w3, w7);
    prep_we<<<(19 * 512 * 64 + 255) / 256, 256>>>(slp_w, b1, b2, b3, b7);

    conv_mma_kernel<<<dim3(8, 128), 512, CONV_SMEM>>>();
    slp_mma_kernel<<<dim3(4, 128), 512, SLP_SMEM>>>(slp_b, out);
}

// round 8
// speedup vs baseline: 7.9864x; 1.0140x over previous
#include <cuda_runtime.h>
#include <cuda_fp16.h>
#include <math.h>
#include <stdint.h>

// ===========================================================================
// TxtNet, single-term fp16 HMMA.16816 (fp32 accum) fed by cp.async.bulk.
// R8: warp tile 64x40 (mt=4) in a 2x4 warp grid, 256 threads, 2 CTAs/SM.
// Cuts SMEM fragment-read replication (~144KB -> ~104KB per chunk) so the
// tensor pipe, not the smem crossbar, binds. 3-deep bulk pipeline,
// producer/consumer full/empty mbarriers. Chunk-major pre-swizzled GMEM.
// Conv: 4 GEMMs, K=ntap*320. SLP: 16384 x 1216 x 512 (x5==x3 fold).
// ===========================================================================

#define P_TOT 16384

// conv smem: A 16K + B 20K per buffer, 3 buffers
#define CH_A 0
#define CH_B 16384
#define CH_BUF 36864
#define C_NBUF 3
#define CONV_SMEM (C_NBUF * CH_BUF + 128)
// slp smem: A 16K + B 16K per buffer, 3 buffers
#define SL_A 0
#define SL_B 16384
#define SL_BUF 32768
#define S_NBUF 3
#define SLP_SMEM (S_NBUF * SL_BUF + 128)

// ------------------------- device scratch (zero-init) ----------------------
__device__ __half g_xc[32 * 5 * 528 * 64];    // [b][kc][row 528 pad][64] sw(row&7)
__device__ __half g_wcc[65 * 320 * 64];       // [slab][oc][64] sw(oc&7)
__device__ __half g_hc[19 * 16384 * 64];      // [kc][pos][64] sw(pos&7)
__device__ __half g_wec[19 * 512 * 64];       // [kc][oc][64] sw(oc&7)
__device__ float g_bconv[1200];

__constant__ int c_off[13] = {0,  0, 1,  -1, 0, 1,  -3, -2, -1, 0, 1, 2, 3};
__constant__ int c_base[4] = {0, 1, 3, 6};
__constant__ int c_nch[4]  = {5, 10, 15, 35};
__constant__ int c_sb[4]   = {0, 5, 15, 30};

// ------------------------- asm helpers -------------------------------------
__device__ __forceinline__ uint32_t smem_u32(const void* p) {
    uint32_t a;
    asm("{ .reg .u64 t; cvta.to.shared.u64 t, %1; cvt.u32.u64 %0, t; }"
        : "=r"(a) : "l"(p));
    return a;
}
#define BULK_G2S(dst, src, bytes, mbar)                                        \
    asm volatile(                                                              \
        "cp.async.bulk.shared::cluster.global.mbarrier::complete_tx::bytes "   \
        "[%0], [%1], %2, [%3];"                                                \
        :: "r"(dst), "l"(src), "r"(bytes), "r"(mbar) : "memory")
#define MBAR_INIT(a, c) \
    asm volatile("mbarrier.init.shared.b64 [%0], %1;" :: "r"(a), "r"(c) : "memory")
#define MBAR_EXPECT_TX(a, b) \
    asm volatile("mbarrier.arrive.expect_tx.shared.b64 _, [%0], %1;" \
                 :: "r"(a), "r"(b) : "memory")
#define MBAR_ARRIVE(a) \
    asm volatile("mbarrier.arrive.shared.b64 _, [%0];" :: "r"(a) : "memory")
#define FENCE_ASYNC() \
    asm volatile("fence.proxy.async.shared::cta;" ::: "memory")
__device__ __forceinline__ void mbar_wait(uint32_t a, uint32_t ph) {
    asm volatile(
        "{\n .reg .pred P;\nW%=:\n"
        " mbarrier.try_wait.parity.acquire.cta.shared::cta.b64 P, [%0], %1, 0x989680;\n"
        " @!P bra W%=;\n}"
        :: "r"(a), "r"(ph) : "memory");
}
#define LDSM4(R, A) \
    asm volatile("ldmatrix.sync.aligned.m8n8.x4.shared.b16 {%0,%1,%2,%3}, [%4];" \
                 : "=r"((R)[0]), "=r"((R)[1]), "=r"((R)[2]), "=r"((R)[3]) : "r"(A))
#define LDSM2(R, A) \
    asm volatile("ldmatrix.sync.aligned.m8n8.x2.shared.b16 {%0,%1}, [%2];" \
                 : "=r"((R)[0]), "=r"((R)[1]) : "r"(A))

__device__ __forceinline__ void mma16816(float* d, const uint32_t* a,
                                         const uint32_t* b) {
    asm volatile(
        "mma.sync.aligned.m16n8k16.row.col.f32.f16.f16.f32 "
        "{%0,%1,%2,%3}, {%4,%5,%6,%7}, {%8,%9}, {%0,%1,%2,%3};"
        : "+f"(d[0]), "+f"(d[1]), "+f"(d[2]), "+f"(d[3])
        : "r"(a[0]), "r"(a[1]), "r"(a[2]), "r"(a[3]), "r"(b[0]), "r"(b[1]));
}

// ------------------------- core compute ------------------------------------
// MT m16-subtiles, NT n8-subtiles per warp. Warp grid 2 (wm) x 4 (wn).
template <int MT, int NT>
__device__ __forceinline__ void compute_buf(uint32_t Ah, uint32_t Bh,
                                            float (&acc)[MT][NT][4],
                                            int wm, int wn, int lane, int rmA) {
    const int hi16 = lane >> 4;
    const int sbB = (lane >> 3) & 1;
    const int rmB = lane & 7;
    const uint32_t aRow  = (uint32_t)(wm * (MT * 16) + (lane & 15)) * 128;
    const uint32_t bRow  = (uint32_t)(wn * (NT * 8) + (lane & 7) +
                                      ((lane >> 4) & 1) * 8) * 128;
    const uint32_t bRow2 = (uint32_t)(wn * (NT * 8) + (NT - 1) * 8 +
                                      (lane & 7)) * 128;
#pragma unroll
    for (int kk = 0; kk < 4; ++kk) {
        const uint32_t sA = (uint32_t)(((kk * 2 + hi16) ^ rmA) << 4);
        const uint32_t sB = (uint32_t)(((kk * 2 + sbB) ^ rmB) << 4);
        uint32_t ah[MT][4];
#pragma unroll
        for (int mt = 0; mt < MT; ++mt) {
            LDSM4(ah[mt], Ah + aRow + mt * 2048 + sA);
        }
#pragma unroll
        for (int p = 0; p < NT / 2; ++p) {
            uint32_t bh[4];
            LDSM4(bh, Bh + bRow + p * 2048 + sB);
#pragma unroll
            for (int q = 0; q < 2; ++q)
#pragma unroll
                for (int mt = 0; mt < MT; ++mt)
                    mma16816(acc[mt][p * 2 + q], ah[mt], bh + q * 2);
        }
        if (NT & 1) {
            uint32_t bh[2];
            LDSM2(bh, Bh + bRow2 + sB);
#pragma unroll
            for (int mt = 0; mt < MT; ++mt)
                mma16816(acc[mt][NT - 1], ah[mt], bh);
        }
    }
}

// ------------------------- prep kernels ------------------------------------
__global__ void prep_x(const float* __restrict__ x) {
    int idx = blockIdx.x * 256 + threadIdx.x;
    if (idx >= 32 * 5 * 528 * 64) return;
    int j = idx & 63;
    int rest = idx >> 6;
    int r = rest % 528; rest /= 528;
    int kc = rest % 5;
    int b = rest / 5;
    int rr = r - 8; rr = rr < 0 ? 0 : (rr > 511 ? 511 : rr);
    int c = kc * 64 + j;
    float v = (c < 300) ? x[((size_t)(b * 512 + rr)) * 300 + c] : 0.f;
    int pir = (((j >> 3) ^ (r & 7)) << 3) | (j & 7);
    g_xc[((size_t)((b * 5 + kc) * 528 + r)) * 64 + pir] = __float2half_rn(v);
}

__global__ void prep_wc(const float* __restrict__ w1, const float* __restrict__ w2,
                        const float* __restrict__ w3, const float* __restrict__ w7) {
    int idx = blockIdx.x * 256 + threadIdx.x;
    if (idx >= 65 * 320 * 64) return;
    int j = idx & 63;
    int oc = (idx >> 6) % 320;
    int s = (idx >> 6) / 320;
    int conv = (s < 5) ? 0 : (s < 15) ? 1 : (s < 30) ? 2 : 3;
    int sb = (conv == 0) ? 0 : (conv == 1) ? 5 : (conv == 2) ? 15 : 30;
    int rel = s - sb;
    int tap = rel / 5, kc = rel % 5;
    int ic = kc * 64 + j;
    float v = 0.f;
    if (oc < 300 && ic < 300) {
        if (conv == 0)      v = w1[(oc * 300 + ic)];
        else if (conv == 1) v = w2[(oc * 300 + ic) * 2 + tap];
        else if (conv == 2) v = w3[(oc * 300 + ic) * 3 + tap];
        else                v = w7[(oc * 300 + ic) * 7 + tap];
    }
    int pir = (((j >> 3) ^ (oc & 7)) << 3) | (j & 7);
    g_wcc[((size_t)(s * 320 + oc)) * 64 + pir] = __float2half_rn(v);
}

__global__ void prep_we(const float* __restrict__ slp_w,
                        const float* __restrict__ b1, const float* __restrict__ b2,
                        const float* __restrict__ b3, const float* __restrict__ b7) {
    int idx = blockIdx.x * 256 + threadIdx.x;
    if (idx < 19 * 512 * 64) {
        int j = idx & 63;
        int oc = (idx >> 6) & 511;
        int kc = idx >> 15;
        int ic = kc * 64 + j;
        float v = 0.f;
        if (ic < 600)       v = slp_w[oc * 1500 + ic];
        else if (ic < 900)  v = slp_w[oc * 1500 + ic] + slp_w[oc * 1500 + ic + 300];
        else if (ic < 1200) v = slp_w[oc * 1500 + ic + 300];
        int pir = (((j >> 3) ^ (oc & 7)) << 3) | (j & 7);
        g_wec[((size_t)(kc * 512 + oc)) * 64 + pir] = __float2half_rn(v);
    }
    if (idx < 1200) {
        int conv = idx / 300, oc = idx % 300;
        const float* b = (conv == 0) ? b1 : (conv == 1) ? b2 : (conv == 2) ? b3 : b7;
        g_bconv[idx] = b[oc];
    }
}

// ------------------------- conv GEMM kernel (BM=128, BN=160) ---------------
__global__ __launch_bounds__(256, 2)
void conv_mma_kernel() {
    extern __shared__ char sm[];
    const uint32_t smb = smem_u32(sm);
    const uint32_t mbF = smb + C_NBUF * CH_BUF;          // full barriers
    const uint32_t mbE = mbF + C_NBUF * 8;               // empty barriers
    const int tid = threadIdx.x, lane = tid & 31, wid = tid >> 5;
    const int wm = wid >> 2, wn = wid & 3;               // 2 x 4 warps
    const int quad = lane >> 2, kp2 = (lane & 3) * 2;

    const int conv = 3 - (int)(blockIdx.x >> 1);         // long convs first
    const int oc0  = (blockIdx.x & 1) * 160;
    const int pos0 = blockIdx.y * 128;
    const int bat = pos0 >> 9, l0 = pos0 & 511;
    const int nc = c_nch[conv];
    const int sbase = c_sb[conv];
    const int tb = c_base[conv];

    if (tid == 0) {
#pragma unroll
        for (int i = 0; i < C_NBUF; ++i) {
            MBAR_INIT(mbF + i * 8, 1);
            MBAR_INIT(mbE + i * 8, 8);
        }
        FENCE_ASYNC();
    }
    __syncthreads();

    float acc[4][5][4];
#pragma unroll
    for (int mt = 0; mt < 4; ++mt)
#pragma unroll
        for (int nt = 0; nt < 5; ++nt)
#pragma unroll
            for (int e = 0; e < 4; ++e) acc[mt][nt][e] = 0.f;

    auto issue = [&](int ch, int buf) {  // thread 0 only
        int tap = ch / 5, kc = ch - tap * 5;
        int dlt = c_off[tb + tap];
        const char* a = (const char*)g_xc +
            ((size_t)((bat * 5 + kc) * 528 + 8 + l0 + dlt)) * 128;
        const char* b = (const char*)g_wcc +
            ((size_t)((sbase + ch) * 320 + oc0)) * 128;
        uint32_t d = smb + buf * CH_BUF;
        uint32_t m = mbF + buf * 8;
        MBAR_EXPECT_TX(m, CH_BUF);
        BULK_G2S(d + CH_A, a, 16384, m);
        BULK_G2S(d + CH_B, b, 20480, m);
    };

    if (tid == 0) {
#pragma unroll
        for (int i = 0; i < C_NBUF; ++i)
            if (i < nc) issue(i, i);
    }

    int buf = 0, ph = 0;
    for (int ch = 0; ch < nc; ++ch) {
        mbar_wait(mbF + buf * 8, ph);
        int tap = ch / 5;
        int adj = (8 + c_off[tb + tap]) & 7;             // A swizzle phase
        int rmA = ((lane & 15) + adj) & 7;
        uint32_t d = smb + buf * CH_BUF;
        compute_buf<4, 5>(d + CH_A, d + CH_B, acc, wm, wn, lane, rmA);
        __syncwarp();
        if (lane == 0) MBAR_ARRIVE(mbE + buf * 8);
        if (tid == 0 && ch + C_NBUF < nc) {
            mbar_wait(mbE + buf * 8, ph);                // all 8 warps done
            issue(ch + C_NBUF, buf);
        }
        if (++buf == C_NBUF) { buf = 0; ph ^= 1; }
    }

    // epilogue: tanh(acc + bias) -> chunked+swizzled fp16 h
#pragma unroll
    for (int mt = 0; mt < 4; ++mt) {
        int r0 = pos0 + wm * 64 + mt * 16 + quad;
#pragma unroll
        for (int nt = 0; nt < 5; ++nt) {
            int col = oc0 + wn * 40 + nt * 8 + kp2;
            if (col >= 300) continue;
            int gc = conv * 300 + col;
            int kc = gc >> 6, j = gc & 63;
            float bi0 = g_bconv[gc], bi1 = g_bconv[gc + 1];
#pragma unroll
            for (int half = 0; half < 2; ++half) {
                int r = r0 + half * 8;
                __half2 hv;
                hv.x = __float2half_rn(tanhf(acc[mt][nt][half * 2 + 0] + bi0));
                hv.y = __float2half_rn(tanhf(acc[mt][nt][half * 2 + 1] + bi1));
                int pir = (((j >> 3) ^ (r & 7)) << 3) | (j & 7);
                *(__half2*)(g_hc + ((size_t)kc * 16384 + r) * 64 + pir) = hv;
            }
        }
    }
}

// ------------------------- SLP GEMM kernel (BM=128, BN=128) ----------------
__global__ __launch_bounds__(256, 2)
void slp_mma_kernel(const float* __restrict__ slp_b, float* __restrict__ out) {
    extern __shared__ char sm[];
    const uint32_t smb = smem_u32(sm);
    const uint32_t mbF = smb + S_NBUF * SL_BUF;
    const uint32_t mbE = mbF + S_NBUF * 8;
    const int tid = threadIdx.x, lane = tid & 31, wid = tid >> 5;
    const int wm = wid >> 2, wn = wid & 3;
    const int quad = lane >> 2, kp2 = (lane & 3) * 2;
    const int oc0  = blockIdx.x * 128;
    const int pos0 = blockIdx.y * 128;
    const int nc = 19;
    const int rmA = lane & 7;

    if (tid == 0) {
#pragma unroll
        for (int i = 0; i < S_NBUF; ++i) {
            MBAR_INIT(mbF + i * 8, 1);
            MBAR_INIT(mbE + i * 8, 8);
        }
        FENCE_ASYNC();
    }
    __syncthreads();

    float acc[4][4][4];
#pragma unroll
    for (int mt = 0; mt < 4; ++mt)
#pragma unroll
        for (int nt = 0; nt < 4; ++nt)
#pragma unroll
            for (int e = 0; e < 4; ++e) acc[mt][nt][e] = 0.f;

    auto issue = [&](int ch, int buf) {
        const char* a = (const char*)g_hc + ((size_t)ch * 16384 + pos0) * 128;
        const char* b = (const char*)g_wec + ((size_t)ch * 512 + oc0) * 128;
        uint32_t d = smb + buf * SL_BUF;
        uint32_t m = mbF + buf * 8;
        MBAR_EXPECT_TX(m, SL_BUF);
        BULK_G2S(d + SL_A, a, 16384, m);
        BULK_G2S(d + SL_B, b, 16384, m);
    };

    if (tid == 0) {
#pragma unroll
        for (int i = 0; i < S_NBUF; ++i)
            if (i < nc) issue(i, i);
    }

    int buf = 0, ph = 0;
    for (int ch = 0; ch < nc; ++ch) {
        mbar_wait(mbF + buf * 8, ph);
        uint32_t d = smb + buf * SL_BUF;
        compute_buf<4, 4>(d + SL_A, d + SL_B, acc, wm, wn, lane, rmA);
        __syncwarp();
        if (lane == 0) MBAR_ARRIVE(mbE + buf * 8);
        if (tid == 0 && ch + S_NBUF < nc) {
            mbar_wait(mbE + buf * 8, ph);
            issue(ch + S_NBUF, buf);
        }
        if (++buf == S_NBUF) { buf = 0; ph ^= 1; }
    }

#pragma unroll
    for (int mt = 0; mt < 4; ++mt) {
        int r0 = pos0 + wm * 64 + mt * 16 + quad;
#pragma unroll
        for (int nt = 0; nt < 4; ++nt) {
            int col = oc0 + wn * 32 + nt * 8 + kp2;
            float bi0 = slp_b[col], bi1 = slp_b[col + 1];
#pragma unroll
            for (int half = 0; half < 2; ++half) {
                int r = r0 + half * 8;
                float2 v;
                v.x = tanhf(acc[mt][nt][half * 2 + 0] + bi0);
                v.y = tanhf(acc[mt][nt][half * 2 + 1] + bi1);
                *(float2*)(out + (size_t)r * 512 + col) = v;
            }
        }
    }
}

// ------------------------- launch ------------------------------------------
extern "C" void kernel_launch(void* const* d_in, const int* in_sizes, int n_in,
                              void* d_out, int out_size) {
    const float* x     = (const float*)d_in[0];
    const float* w1    = (const float*)d_in[1];
    const float* b1    = (const float*)d_in[2];
    const float* w2    = (const float*)d_in[3];
    const float* b2    = (const float*)d_in[4];
    const float* w3    = (const float*)d_in[5];
    const float* b3    = (const float*)d_in[6];
    const float* w7    = (const float*)d_in[7];
    const float* b7    = (const float*)d_in[8];
    const float* slp_w = (const float*)d_in[9];
    const float* slp_b = (const float*)d_in[10];
    float* out = (float*)d_out;

    cudaFuncSetAttribute(conv_mma_kernel, cudaFuncAttributeMaxDynamicSharedMemorySize, CONV_SMEM);
    cudaFuncSetAttribute(slp_mma_kernel,  cudaFuncAttributeMaxDynamicSharedMemorySize, SLP_SMEM);

    prep_x<<<(32 * 5 * 528 * 64 + 255) / 256, 256>>>(x);
    prep_wc<<<(65 * 320 * 64 + 255) / 256, 256>>>(w1, w2, w3, w7);
    prep_we<<<(19 * 512 * 64 + 255) / 256, 256>>>(slp_w, b1, b2, b3, b7);

    conv_mma_kernel<<<dim3(8, 128), 256, CONV_SMEM>>>();
    slp_mma_kernel<<<dim3(4, 128), 256, SLP_SMEM>>>(slp_b, out);
}